// round 3
// baseline (speedup 1.0000x reference)
#include <cuda_runtime.h>
#include <cstdint>
#include <math.h>

// ---------------- problem constants ----------------
#define BB 8
#define NN 1000
#define EE 4000
#define HH 256

// ---------------- GEMM tile config -----------------
#define TBM 128
#define TBN 128
#define TBK 16
#define ASTR 20              // padded row stride of A smem tile [m][k]
#define BSTR 136             // padded row stride of B smem tile [k][n]
#define A_BUF (TBM*ASTR)     // 2560 floats
#define B_BUF (TBK*BSTR)     // 2176 floats
// 3 precision levels (hi/mid/lo) x double buffer
#define SMEM_FLOATS (6*A_BUF + 6*B_BUF)
#define SMEM_BYTES (SMEM_FLOATS * 4)      // 113664 bytes

// ---------------- scratch (static device globals; no allocation) ----------------
__device__ float g_tmp1[BB*EE*HH];
__device__ float g_tmp2[BB*EE*HH];
__device__ float g_bw  [BB*NN*HH];
__device__ float g_fw  [BB*NN*HH];
__device__ float g_agg [BB*NN*HH];
__device__ float g_zg  [BB*NN*HH];
__device__ float g_rg  [BB*NN*HH];
__device__ float g_nf1 [BB*NN*HH];
__device__ float g_cat4[BB*NN*4*HH];
__device__ float g_hx  [BB*NN*2*HH];
__device__ float g_cat2[BB*NN*2*HH];
__device__ float g_WfT [4*HH*HH];
__device__ float g_WzT [2*HH*HH];
__device__ float g_WrT [2*HH*HH];
__device__ float g_WtT [2*HH*HH];

// ---------------- helpers ----------------
__device__ __forceinline__ uint32_t f2tf(float f) {
    uint32_t u; asm("cvt.rna.tf32.f32 %0, %1;" : "=r"(u) : "f"(f)); return u;
}

__device__ __forceinline__ void mma8(float* d, const uint32_t* a, const uint32_t* b) {
    asm volatile(
        "mma.sync.aligned.m16n8k8.row.col.f32.tf32.tf32.f32 "
        "{%0,%1,%2,%3},{%4,%5,%6,%7},{%8,%9},{%0,%1,%2,%3};"
        : "+f"(d[0]), "+f"(d[1]), "+f"(d[2]), "+f"(d[3])
        : "r"(a[0]), "r"(a[1]), "r"(a[2]), "r"(a[3]), "r"(b[0]), "r"(b[1]));
}

// split x into 3 tf32 values: x ~= h + m + l, residual ~ 2^-33 |x|
__device__ __forceinline__ void split3(float x, float& h, float& m, float& l) {
    uint32_t hu = f2tf(x);
    h = __uint_as_float(hu);
    float r1 = __fadd_rn(x, -h);
    uint32_t mu = f2tf(r1);
    m = __uint_as_float(mu);
    float r2 = __fadd_rn(r1, -m);
    uint32_t lu = f2tf(r2);
    l = __uint_as_float(lu);
}

// MODE: 0=store, 1=sigmoid, 2=gated fusion (bias=bf, aux1=fw, aux2=bw), 3=GRU out (aux1=z, aux2=h_old)
// FOLD: fold fresh accumulator into master every FOLD k-tiles (limits partial-sum magnitude noise)
template<int TRANSA, int MODE, int FOLD>
__global__ void __launch_bounds__(256)
gemm_k(const float* __restrict__ A, const float* __restrict__ B, float* __restrict__ C,
       int M, int K, int lda,
       long long sA, long long sB, long long sC,
       const float* __restrict__ bias,
       const float* __restrict__ aux1, const float* __restrict__ aux2)
{
    extern __shared__ float sm[];
    float* sAh = sm;
    float* sAm = sm + 2*A_BUF;
    float* sAl = sm + 4*A_BUF;
    float* sBh = sm + 6*A_BUF;
    float* sBm = sm + 6*A_BUF + 2*B_BUF;
    float* sBl = sm + 6*A_BUF + 4*B_BUF;

    const int tid = threadIdx.x;
    const int m0 = blockIdx.y * TBM;
    const int n0 = blockIdx.x * TBN;
    const float* Ab = A + (long long)blockIdx.z * sA;
    const float* Bb = B + (long long)blockIdx.z * sB;
    float* Cb = C + (long long)blockIdx.z * sC;

    const int lane = tid & 31, warp = tid >> 5;
    const int wm = warp >> 2, wn = warp & 3;       // 2 x 4 warps -> 64x32 warp tiles
    const int gid = lane >> 2, tig = lane & 3;

    float acc[64];   // fresh chunk accumulator (mma target)
    float mst[64];   // master accumulator
#pragma unroll
    for (int i = 0; i < 64; i++) { acc[i] = 0.f; mst[i] = 0.f; }

    const int KT = (K + TBK - 1) / TBK;
    float aR[8], bR[8];

    auto loadTiles = [&](int k0) {
#pragma unroll
        for (int it = 0; it < 2; it++) {
            int linear = tid + it * 256;
            float4 v = make_float4(0.f, 0.f, 0.f, 0.f);
            if (TRANSA == 0) {
                int row = linear >> 2, c4 = (linear & 3) << 2;
                int gr = m0 + row, gc = k0 + c4;
                if (gr < M) {
                    if (gc + 3 < K) {
                        v = *reinterpret_cast<const float4*>(Ab + (size_t)gr * lda + gc);
                    } else {
                        float* p = &v.x;
#pragma unroll
                        for (int j = 0; j < 4; j++)
                            if (gc + j < K) p[j] = Ab[(size_t)gr * lda + gc + j];
                    }
                }
            } else {
                int kk = linear >> 5, m4 = (linear & 31) << 2;
                int gk = k0 + kk, gm = m0 + m4;
                if (gk < K) {
                    if (gm + 3 < M) {
                        v = *reinterpret_cast<const float4*>(Ab + (size_t)gk * lda + gm);
                    } else {
                        float* p = &v.x;
#pragma unroll
                        for (int j = 0; j < 4; j++)
                            if (gm + j < M) p[j] = Ab[(size_t)gk * lda + gm + j];
                    }
                }
            }
            aR[it*4+0] = v.x; aR[it*4+1] = v.y; aR[it*4+2] = v.z; aR[it*4+3] = v.w;

            int kr = linear >> 5, n4 = (linear & 31) << 2;
            int gk2 = k0 + kr;
            float4 w = make_float4(0.f, 0.f, 0.f, 0.f);
            if (gk2 < K)
                w = *reinterpret_cast<const float4*>(Bb + (size_t)gk2 * 256 + n0 + n4);
            bR[it*4+0] = w.x; bR[it*4+1] = w.y; bR[it*4+2] = w.z; bR[it*4+3] = w.w;
        }
    };

    auto storeTiles = [&](int buf) {
        float* ah = sAh + buf * A_BUF; float* am = sAm + buf * A_BUF; float* al = sAl + buf * A_BUF;
        float* bh = sBh + buf * B_BUF; float* bm = sBm + buf * B_BUF; float* bl = sBl + buf * B_BUF;
#pragma unroll
        for (int it = 0; it < 2; it++) {
            int linear = tid + it * 256;
#pragma unroll
            for (int j = 0; j < 4; j++) {
                float h, m, l;
                split3(aR[it*4+j], h, m, l);
                int idx;
                if (TRANSA == 0) { int row = linear >> 2, c4 = (linear & 3) << 2; idx = row*ASTR + c4 + j; }
                else             { int kk  = linear >> 5, m4 = (linear & 31) << 2; idx = (m4+j)*ASTR + kk; }
                ah[idx] = h; am[idx] = m; al[idx] = l;

                split3(bR[it*4+j], h, m, l);
                int kr = linear >> 5, n4 = (linear & 31) << 2;
                int bidx = kr * BSTR + n4 + j;
                bh[bidx] = h; bm[bidx] = m; bl[bidx] = l;
            }
        }
    };

    auto computeTile = [&](int buf) {
        const float* Ah = sAh + buf * A_BUF; const float* Am = sAm + buf * A_BUF; const float* Al = sAl + buf * A_BUF;
        const float* Bh = sBh + buf * B_BUF; const float* Bm = sBm + buf * B_BUF; const float* Bl = sBl + buf * B_BUF;
#pragma unroll
        for (int ks = 0; ks < 2; ks++) {
            int kb = ks * 8;
            uint32_t bh[4][2], bm[4][2], bl[4][2];
#pragma unroll
            for (int ni = 0; ni < 4; ni++) {
                int cc = wn * 32 + ni * 8 + gid;
                bh[ni][0] = __float_as_uint(Bh[(kb+tig)  *BSTR + cc]);
                bh[ni][1] = __float_as_uint(Bh[(kb+tig+4)*BSTR + cc]);
                bm[ni][0] = __float_as_uint(Bm[(kb+tig)  *BSTR + cc]);
                bm[ni][1] = __float_as_uint(Bm[(kb+tig+4)*BSTR + cc]);
                bl[ni][0] = __float_as_uint(Bl[(kb+tig)  *BSTR + cc]);
                bl[ni][1] = __float_as_uint(Bl[(kb+tig+4)*BSTR + cc]);
            }
#pragma unroll
            for (int mi = 0; mi < 4; mi++) {
                int r0 = wm * 64 + mi * 16 + gid;
                uint32_t ah[4], am[4], al[4];
#pragma unroll
                for (int q = 0; q < 4; q++) {
                    int rr = r0 + ((q & 1) ? 8 : 0);
                    int kk = kb + tig + ((q & 2) ? 4 : 0);
                    ah[q] = __float_as_uint(Ah[rr*ASTR + kk]);
                    am[q] = __float_as_uint(Am[rr*ASTR + kk]);
                    al[q] = __float_as_uint(Al[rr*ASTR + kk]);
                }
#pragma unroll
                for (int ni = 0; ni < 4; ni++) {
                    float* a4 = &acc[(mi*4 + ni)*4];
                    mma8(a4, al, bh[ni]);   // lo*hi   (~2^-22)
                    mma8(a4, ah, bl[ni]);   // hi*lo   (~2^-22)
                    mma8(a4, am, bm[ni]);   // mid*mid (~2^-22)
                    mma8(a4, am, bh[ni]);   // mid*hi  (~2^-11)
                    mma8(a4, ah, bm[ni]);   // hi*mid  (~2^-11)
                    mma8(a4, ah, bh[ni]);   // hi*hi
                }
            }
        }
    };

    loadTiles(0);
    storeTiles(0);
    __syncthreads();
    for (int kt = 0; kt < KT; kt++) {
        if (kt + 1 < KT) loadTiles((kt + 1) * TBK);
        computeTile(kt & 1);
        if (((kt + 1) % FOLD) == 0 || kt == KT - 1) {
            // fold fresh chunk into master; keeps fresh-acc magnitudes small
#pragma unroll
            for (int i = 0; i < 64; i++) {
                mst[i] = __fadd_rn(mst[i], acc[i]);
                acc[i] = 0.f;
            }
        }
        if (kt + 1 < KT) storeTiles((kt + 1) & 1);
        __syncthreads();
    }

    // epilogue
#pragma unroll
    for (int mi = 0; mi < 4; mi++) {
#pragma unroll
        for (int ni = 0; ni < 4; ni++) {
            int rB = m0 + wm * 64 + mi * 16 + gid;
            int cB = n0 + wn * 32 + ni * 8 + tig * 2;
#pragma unroll
            for (int rr = 0; rr < 2; rr++) {
                int r = rB + rr * 8;
                if (r < M) {
#pragma unroll
                    for (int c2 = 0; c2 < 2; c2++) {
                        int c = cB + c2;
                        float v = mst[(mi*4 + ni)*4 + rr * 2 + c2];
                        size_t idx = (size_t)r * 256 + c;
                        if (MODE == 0) {
                            Cb[idx] = v;
                        } else if (MODE == 1) {
                            Cb[idx] = 1.f / (1.f + expf(-v));
                        } else if (MODE == 2) {
                            float z = 1.f / (1.f + expf(-(v + bias[c])));
                            Cb[idx] = (1.f - z) * aux1[idx] + z * aux2[idx];
                        } else {
                            float t = tanhf(v);
                            float z = aux1[idx];
                            Cb[idx] = (1.f - z) * aux2[idx] + z * t;
                        }
                    }
                }
            }
        }
    }
}

// ---------------- elementwise kernels ----------------
__global__ void k_build_cat4(const float* __restrict__ fw, const float* __restrict__ bw,
                             float* __restrict__ cat, int total) {
    int i = blockIdx.x * blockDim.x + threadIdx.x;
    if (i >= total) return;
    int row = i >> 8, h = i & 255;
    float f = fw[i], b = bw[i];
    float* c = cat + ((size_t)row << 10) + h;
    c[0] = f; c[256] = b; c[512] = f * b; c[768] = f - b;
}

__global__ void k_build_hx(const float* __restrict__ nf, const float* __restrict__ agg,
                           float* __restrict__ hx, int total) {
    int i = blockIdx.x * blockDim.x + threadIdx.x;
    if (i >= total) return;
    int row = i >> 8, h = i & 255;
    float* p = hx + ((size_t)row << 9) + h;
    p[0] = nf[i]; p[256] = agg[i];
}

__global__ void k_build_cat2(const float* __restrict__ rg, const float* __restrict__ nf,
                             const float* __restrict__ agg, float* __restrict__ c2, int total) {
    int i = blockIdx.x * blockDim.x + threadIdx.x;
    if (i >= total) return;
    int row = i >> 8, h = i & 255;
    float* p = c2 + ((size_t)row << 9) + h;
    p[0] = rg[i] * nf[i]; p[256] = agg[i];
}

__global__ void k_transpose(const float* __restrict__ src, float* __restrict__ dst, int R, int C) {
    __shared__ float t[32][33];
    int bx = blockIdx.x * 32, by = blockIdx.y * 32;
    int x = threadIdx.x, y = threadIdx.y;
#pragma unroll
    for (int j = 0; j < 32; j += 8) {
        int r = by + y + j, c = bx + x;
        if (r < R && c < C) t[y + j][x] = src[(size_t)r * C + c];
    }
    __syncthreads();
#pragma unroll
    for (int j = 0; j < 32; j += 8) {
        int r = bx + y + j, c = by + x;
        if (r < C && c < R) dst[(size_t)r * R + c] = t[x][y + j];
    }
}

// ---------------- host side ----------------
template<int TA, int MODE, int FOLD>
static void rungemm(const float* A, const float* B, float* C,
                    int M, int K, int lda,
                    long long sA, long long sB, long long sC, int batch,
                    const float* bias, const float* a1, const float* a2)
{
    cudaFuncSetAttribute(gemm_k<TA, MODE, FOLD>, cudaFuncAttributeMaxDynamicSharedMemorySize, SMEM_BYTES);
    dim3 grid(2, (M + TBM - 1) / TBM, batch);
    gemm_k<TA, MODE, FOLD><<<grid, 256, SMEM_BYTES>>>(A, B, C, M, K, lda, sA, sB, sC, bias, a1, a2);
}

extern "C" void kernel_launch(void* const* d_in, const int* in_sizes, int n_in,
                              void* d_out, int out_size)
{
    const float* node_feature = (const float*)d_in[0];
    const float* node2edge    = (const float*)d_in[1];
    const float* edge2node    = (const float*)d_in[2];
    const float* Wz = (const float*)d_in[3];
    const float* Wr = (const float*)d_in[4];
    const float* Wt = (const float*)d_in[5];
    const float* Wf = (const float*)d_in[6];
    const float* bf = (const float*)d_in[7];
    float* out = (float*)d_out;

    float *tmp1, *tmp2, *bwP, *fwP, *agg, *zg, *rg, *nf1, *cat4, *hx, *cat2;
    float *WfT, *WzT, *WrT, *WtT;
    cudaGetSymbolAddress((void**)&tmp1, g_tmp1);
    cudaGetSymbolAddress((void**)&tmp2, g_tmp2);
    cudaGetSymbolAddress((void**)&bwP,  g_bw);
    cudaGetSymbolAddress((void**)&fwP,  g_fw);
    cudaGetSymbolAddress((void**)&agg,  g_agg);
    cudaGetSymbolAddress((void**)&zg,   g_zg);
    cudaGetSymbolAddress((void**)&rg,   g_rg);
    cudaGetSymbolAddress((void**)&nf1,  g_nf1);
    cudaGetSymbolAddress((void**)&cat4, g_cat4);
    cudaGetSymbolAddress((void**)&hx,   g_hx);
    cudaGetSymbolAddress((void**)&cat2, g_cat2);
    cudaGetSymbolAddress((void**)&WfT,  g_WfT);
    cudaGetSymbolAddress((void**)&WzT,  g_WzT);
    cudaGetSymbolAddress((void**)&WrT,  g_WrT);
    cudaGetSymbolAddress((void**)&WtT,  g_WtT);

    // transpose weights once per call
    k_transpose<<<dim3(32, 8), dim3(32, 8)>>>(Wf, WfT, 256, 1024);
    k_transpose<<<dim3(16, 8), dim3(32, 8)>>>(Wz, WzT, 256, 512);
    k_transpose<<<dim3(16, 8), dim3(32, 8)>>>(Wr, WrT, 256, 512);
    k_transpose<<<dim3(16, 8), dim3(32, 8)>>>(Wt, WtT, 256, 512);

    const long long sNF = (long long)NN * HH;
    const long long sEH = (long long)EE * HH;
    const long long sPQ = (long long)EE * NN;
    const int TOT = BB * NN * HH;
    const int MR = BB * NN;

    const float* nfIn = node_feature;
    for (int hop = 0; hop < 2; hop++) {
        float* nfOut = (hop == 1) ? out : nf1;

        // tmp1[b,e,h] = sum_n node2edge[b,e,n] * nf[b,n,h]
        rungemm<0, 0, 4>(node2edge, nfIn, tmp1, EE, NN, NN, sPQ, sNF, sEH, BB, nullptr, nullptr, nullptr);
        // tmp2[b,e,h] = sum_n edge2node[b,n,e] * nf[b,n,h]   (A accessed transposed, lda=E)
        rungemm<1, 0, 4>(edge2node, nfIn, tmp2, EE, NN, EE, sPQ, sNF, sEH, BB, nullptr, nullptr, nullptr);
        // bw[b,n,h] = sum_e edge2node[b,n,e] * tmp1[b,e,h]
        rungemm<0, 0, 4>(edge2node, tmp1, bwP, NN, EE, EE, sPQ, sEH, sNF, BB, nullptr, nullptr, nullptr);
        // fw[b,n,h] = sum_e node2edge[b,e,n] * tmp2[b,e,h]   (A transposed, lda=N)
        rungemm<1, 0, 4>(node2edge, tmp2, fwP, NN, EE, NN, sPQ, sEH, sNF, BB, nullptr, nullptr, nullptr);

        // gated fusion
        k_build_cat4<<<TOT / 256, 256>>>(fwP, bwP, cat4, TOT);
        rungemm<0, 2, 1>(cat4, WfT, agg, MR, 4 * HH, 4 * HH, 0, 0, 0, 1, bf, fwP, bwP);

        // GRU step
        k_build_hx<<<TOT / 256, 256>>>(nfIn, agg, hx, TOT);
        rungemm<0, 1, 1>(hx, WzT, zg, MR, 2 * HH, 2 * HH, 0, 0, 0, 1, nullptr, nullptr, nullptr);
        rungemm<0, 1, 1>(hx, WrT, rg, MR, 2 * HH, 2 * HH, 0, 0, 0, 1, nullptr, nullptr, nullptr);
        k_build_cat2<<<TOT / 256, 256>>>(rg, nfIn, agg, cat2, TOT);
        rungemm<0, 3, 1>(cat2, WtT, nfOut, MR, 2 * HH, 2 * HH, 0, 0, 0, 1, nullptr, zg, nfIn);

        nfIn = nfOut;
    }
}

// round 4
// speedup vs baseline: 1.5963x; 1.5963x over previous
#include <cuda_runtime.h>
#include <cstdint>
#include <math.h>

// ---------------- problem constants ----------------
#define BB 8
#define NN 1000
#define EE 4000
#define HH 256

// ---------------- GEMM tile config -----------------
#define TBM 128
#define TBN 128
#define TBK 16
#define ASTR 20              // padded row stride of A smem tile [m][k]
#define BSTR 136             // padded row stride of B smem tile [k][n]
#define A_BUF (TBM*ASTR)     // 2560 floats
#define B_BUF (TBK*BSTR)     // 2176 floats
// 2 precision levels (hi/lo) x double buffer
#define SMEM_FLOATS (4*A_BUF + 4*B_BUF)
#define SMEM_BYTES (SMEM_FLOATS * 4)      // 75776 bytes

// ---------------- scratch (static device globals; no allocation) ----------------
__device__ float g_tmp1[BB*EE*HH];
__device__ float g_tmp2[BB*EE*HH];
__device__ float g_bw  [BB*NN*HH];
__device__ float g_fw  [BB*NN*HH];
__device__ float g_agg [BB*NN*HH];
__device__ float g_zg  [BB*NN*HH];
__device__ float g_rg  [BB*NN*HH];
__device__ float g_nf1 [BB*NN*HH];
__device__ float g_cat4[BB*NN*4*HH];
__device__ float g_hx  [BB*NN*2*HH];
__device__ float g_cat2[BB*NN*2*HH];
__device__ float g_WfT [4*HH*HH];
__device__ float g_WzT [2*HH*HH];
__device__ float g_WrT [2*HH*HH];
__device__ float g_WtT [2*HH*HH];

// ---------------- helpers ----------------
__device__ __forceinline__ uint32_t f2tf(float f) {
    uint32_t u; asm("cvt.rna.tf32.f32 %0, %1;" : "=r"(u) : "f"(f)); return u;
}

__device__ __forceinline__ void mma8(float* d, const uint32_t* a, const uint32_t* b) {
    asm volatile(
        "mma.sync.aligned.m16n8k8.row.col.f32.tf32.tf32.f32 "
        "{%0,%1,%2,%3},{%4,%5,%6,%7},{%8,%9},{%0,%1,%2,%3};"
        : "+f"(d[0]), "+f"(d[1]), "+f"(d[2]), "+f"(d[3])
        : "r"(a[0]), "r"(a[1]), "r"(a[2]), "r"(a[3]), "r"(b[0]), "r"(b[1]));
}

// split x into 2 tf32 values: x ~= h + l, residual ~ 2^-24 |x| (3xTF32 scheme)
__device__ __forceinline__ void split2(float x, float& h, float& l) {
    uint32_t hu = f2tf(x);
    h = __uint_as_float(hu);
    float r1 = __fadd_rn(x, -h);
    uint32_t lu = f2tf(r1);
    l = __uint_as_float(lu);
}

// MODE: 0=store, 1=sigmoid, 2=gated fusion (bias=bf, aux1=fw, aux2=bw), 3=GRU out (aux1=z, aux2=h_old)
// FOLD: fold fresh accumulator into master every FOLD k-tiles (limits partial-sum rounding noise)
template<int TRANSA, int MODE, int FOLD>
__global__ void __launch_bounds__(256)
gemm_k(const float* __restrict__ A, const float* __restrict__ B, float* __restrict__ C,
       int M, int K, int lda,
       long long sA, long long sB, long long sC,
       const float* __restrict__ bias,
       const float* __restrict__ aux1, const float* __restrict__ aux2)
{
    extern __shared__ float sm[];
    float* sAh = sm;
    float* sAl = sm + 2*A_BUF;
    float* sBh = sm + 4*A_BUF;
    float* sBl = sm + 4*A_BUF + 2*B_BUF;

    const int tid = threadIdx.x;
    const int m0 = blockIdx.y * TBM;
    const int n0 = blockIdx.x * TBN;
    const float* Ab = A + (long long)blockIdx.z * sA;
    const float* Bb = B + (long long)blockIdx.z * sB;
    float* Cb = C + (long long)blockIdx.z * sC;

    const int lane = tid & 31, warp = tid >> 5;
    const int wm = warp >> 2, wn = warp & 3;       // 2 x 4 warps -> 64x32 warp tiles
    const int gid = lane >> 2, tig = lane & 3;

    float acc[64];   // fresh chunk accumulator (mma target)
    float mst[64];   // master accumulator
#pragma unroll
    for (int i = 0; i < 64; i++) { acc[i] = 0.f; mst[i] = 0.f; }

    const int KT = (K + TBK - 1) / TBK;
    float aR[8], bR[8];

    auto loadTiles = [&](int k0) {
#pragma unroll
        for (int it = 0; it < 2; it++) {
            int linear = tid + it * 256;
            float4 v = make_float4(0.f, 0.f, 0.f, 0.f);
            if (TRANSA == 0) {
                int row = linear >> 2, c4 = (linear & 3) << 2;
                int gr = m0 + row, gc = k0 + c4;
                if (gr < M) {
                    if (gc + 3 < K) {
                        v = *reinterpret_cast<const float4*>(Ab + (size_t)gr * lda + gc);
                    } else {
                        float* p = &v.x;
#pragma unroll
                        for (int j = 0; j < 4; j++)
                            if (gc + j < K) p[j] = Ab[(size_t)gr * lda + gc + j];
                    }
                }
            } else {
                int kk = linear >> 5, m4 = (linear & 31) << 2;
                int gk = k0 + kk, gm = m0 + m4;
                if (gk < K) {
                    if (gm + 3 < M) {
                        v = *reinterpret_cast<const float4*>(Ab + (size_t)gk * lda + gm);
                    } else {
                        float* p = &v.x;
#pragma unroll
                        for (int j = 0; j < 4; j++)
                            if (gm + j < M) p[j] = Ab[(size_t)gk * lda + gm + j];
                    }
                }
            }
            aR[it*4+0] = v.x; aR[it*4+1] = v.y; aR[it*4+2] = v.z; aR[it*4+3] = v.w;

            int kr = linear >> 5, n4 = (linear & 31) << 2;
            int gk2 = k0 + kr;
            float4 w = make_float4(0.f, 0.f, 0.f, 0.f);
            if (gk2 < K)
                w = *reinterpret_cast<const float4*>(Bb + (size_t)gk2 * 256 + n0 + n4);
            bR[it*4+0] = w.x; bR[it*4+1] = w.y; bR[it*4+2] = w.z; bR[it*4+3] = w.w;
        }
    };

    auto storeTiles = [&](int buf) {
        float* ah = sAh + buf * A_BUF; float* al = sAl + buf * A_BUF;
        float* bh = sBh + buf * B_BUF; float* bl = sBl + buf * B_BUF;
#pragma unroll
        for (int it = 0; it < 2; it++) {
            int linear = tid + it * 256;
#pragma unroll
            for (int j = 0; j < 4; j++) {
                float h, l;
                split2(aR[it*4+j], h, l);
                int idx;
                if (TRANSA == 0) { int row = linear >> 2, c4 = (linear & 3) << 2; idx = row*ASTR + c4 + j; }
                else             { int kk  = linear >> 5, m4 = (linear & 31) << 2; idx = (m4+j)*ASTR + kk; }
                ah[idx] = h; al[idx] = l;

                split2(bR[it*4+j], h, l);
                int kr = linear >> 5, n4 = (linear & 31) << 2;
                int bidx = kr * BSTR + n4 + j;
                bh[bidx] = h; bl[bidx] = l;
            }
        }
    };

    auto computeTile = [&](int buf) {
        const float* Ah = sAh + buf * A_BUF; const float* Al = sAl + buf * A_BUF;
        const float* Bh = sBh + buf * B_BUF; const float* Bl = sBl + buf * B_BUF;
#pragma unroll
        for (int ks = 0; ks < 2; ks++) {
            int kb = ks * 8;
            uint32_t bh[4][2], bl[4][2];
#pragma unroll
            for (int ni = 0; ni < 4; ni++) {
                int cc = wn * 32 + ni * 8 + gid;
                bh[ni][0] = __float_as_uint(Bh[(kb+tig)  *BSTR + cc]);
                bh[ni][1] = __float_as_uint(Bh[(kb+tig+4)*BSTR + cc]);
                bl[ni][0] = __float_as_uint(Bl[(kb+tig)  *BSTR + cc]);
                bl[ni][1] = __float_as_uint(Bl[(kb+tig+4)*BSTR + cc]);
            }
#pragma unroll
            for (int mi = 0; mi < 4; mi++) {
                int r0 = wm * 64 + mi * 16 + gid;
                uint32_t ah[4], al[4];
#pragma unroll
                for (int q = 0; q < 4; q++) {
                    int rr = r0 + ((q & 1) ? 8 : 0);
                    int kk = kb + tig + ((q & 2) ? 4 : 0);
                    ah[q] = __float_as_uint(Ah[rr*ASTR + kk]);
                    al[q] = __float_as_uint(Al[rr*ASTR + kk]);
                }
#pragma unroll
                for (int ni = 0; ni < 4; ni++) {
                    float* a4 = &acc[(mi*4 + ni)*4];
                    mma8(a4, al, bh[ni]);   // lo*hi  (~2^-12)
                    mma8(a4, ah, bl[ni]);   // hi*lo  (~2^-12)
                    mma8(a4, ah, bh[ni]);   // hi*hi
                }
            }
        }
    };

    loadTiles(0);
    storeTiles(0);
    __syncthreads();
    for (int kt = 0; kt < KT; kt++) {
        if (kt + 1 < KT) loadTiles((kt + 1) * TBK);
        computeTile(kt & 1);
        if (((kt + 1) % FOLD) == 0 || kt == KT - 1) {
            // fold fresh chunk into master; keeps fresh-acc magnitudes small
#pragma unroll
            for (int i = 0; i < 64; i++) {
                mst[i] = __fadd_rn(mst[i], acc[i]);
                acc[i] = 0.f;
            }
        }
        if (kt + 1 < KT) storeTiles((kt + 1) & 1);
        __syncthreads();
    }

    // epilogue
#pragma unroll
    for (int mi = 0; mi < 4; mi++) {
#pragma unroll
        for (int ni = 0; ni < 4; ni++) {
            int rB = m0 + wm * 64 + mi * 16 + gid;
            int cB = n0 + wn * 32 + ni * 8 + tig * 2;
#pragma unroll
            for (int rr = 0; rr < 2; rr++) {
                int r = rB + rr * 8;
                if (r < M) {
#pragma unroll
                    for (int c2 = 0; c2 < 2; c2++) {
                        int c = cB + c2;
                        float v = mst[(mi*4 + ni)*4 + rr * 2 + c2];
                        size_t idx = (size_t)r * 256 + c;
                        if (MODE == 0) {
                            Cb[idx] = v;
                        } else if (MODE == 1) {
                            Cb[idx] = 1.f / (1.f + expf(-v));
                        } else if (MODE == 2) {
                            float z = 1.f / (1.f + expf(-(v + bias[c])));
                            Cb[idx] = (1.f - z) * aux1[idx] + z * aux2[idx];
                        } else {
                            float t = tanhf(v);
                            float z = aux1[idx];
                            Cb[idx] = (1.f - z) * aux2[idx] + z * t;
                        }
                    }
                }
            }
        }
    }
}

// ---------------- elementwise kernels ----------------
__global__ void k_build_cat4(const float* __restrict__ fw, const float* __restrict__ bw,
                             float* __restrict__ cat, int total) {
    int i = blockIdx.x * blockDim.x + threadIdx.x;
    if (i >= total) return;
    int row = i >> 8, h = i & 255;
    float f = fw[i], b = bw[i];
    float* c = cat + ((size_t)row << 10) + h;
    c[0] = f; c[256] = b; c[512] = f * b; c[768] = f - b;
}

__global__ void k_build_hx(const float* __restrict__ nf, const float* __restrict__ agg,
                           float* __restrict__ hx, int total) {
    int i = blockIdx.x * blockDim.x + threadIdx.x;
    if (i >= total) return;
    int row = i >> 8, h = i & 255;
    float* p = hx + ((size_t)row << 9) + h;
    p[0] = nf[i]; p[256] = agg[i];
}

__global__ void k_build_cat2(const float* __restrict__ rg, const float* __restrict__ nf,
                             const float* __restrict__ agg, float* __restrict__ c2, int total) {
    int i = blockIdx.x * blockDim.x + threadIdx.x;
    if (i >= total) return;
    int row = i >> 8, h = i & 255;
    float* p = c2 + ((size_t)row << 9) + h;
    p[0] = rg[i] * nf[i]; p[256] = agg[i];
}

__global__ void k_transpose(const float* __restrict__ src, float* __restrict__ dst, int R, int C) {
    __shared__ float t[32][33];
    int bx = blockIdx.x * 32, by = blockIdx.y * 32;
    int x = threadIdx.x, y = threadIdx.y;
#pragma unroll
    for (int j = 0; j < 32; j += 8) {
        int r = by + y + j, c = bx + x;
        if (r < R && c < C) t[y + j][x] = src[(size_t)r * C + c];
    }
    __syncthreads();
#pragma unroll
    for (int j = 0; j < 32; j += 8) {
        int r = bx + y + j, c = by + x;
        if (r < C && c < R) dst[(size_t)r * R + c] = t[x][y + j];
    }
}

// ---------------- host side ----------------
template<int TA, int MODE, int FOLD>
static void rungemm(const float* A, const float* B, float* C,
                    int M, int K, int lda,
                    long long sA, long long sB, long long sC, int batch,
                    const float* bias, const float* a1, const float* a2)
{
    cudaFuncSetAttribute(gemm_k<TA, MODE, FOLD>, cudaFuncAttributeMaxDynamicSharedMemorySize, SMEM_BYTES);
    dim3 grid(2, (M + TBM - 1) / TBM, batch);
    gemm_k<TA, MODE, FOLD><<<grid, 256, SMEM_BYTES>>>(A, B, C, M, K, lda, sA, sB, sC, bias, a1, a2);
}

extern "C" void kernel_launch(void* const* d_in, const int* in_sizes, int n_in,
                              void* d_out, int out_size)
{
    const float* node_feature = (const float*)d_in[0];
    const float* node2edge    = (const float*)d_in[1];
    const float* edge2node    = (const float*)d_in[2];
    const float* Wz = (const float*)d_in[3];
    const float* Wr = (const float*)d_in[4];
    const float* Wt = (const float*)d_in[5];
    const float* Wf = (const float*)d_in[6];
    const float* bf = (const float*)d_in[7];
    float* out = (float*)d_out;

    float *tmp1, *tmp2, *bwP, *fwP, *agg, *zg, *rg, *nf1, *cat4, *hx, *cat2;
    float *WfT, *WzT, *WrT, *WtT;
    cudaGetSymbolAddress((void**)&tmp1, g_tmp1);
    cudaGetSymbolAddress((void**)&tmp2, g_tmp2);
    cudaGetSymbolAddress((void**)&bwP,  g_bw);
    cudaGetSymbolAddress((void**)&fwP,  g_fw);
    cudaGetSymbolAddress((void**)&agg,  g_agg);
    cudaGetSymbolAddress((void**)&zg,   g_zg);
    cudaGetSymbolAddress((void**)&rg,   g_rg);
    cudaGetSymbolAddress((void**)&nf1,  g_nf1);
    cudaGetSymbolAddress((void**)&cat4, g_cat4);
    cudaGetSymbolAddress((void**)&hx,   g_hx);
    cudaGetSymbolAddress((void**)&cat2, g_cat2);
    cudaGetSymbolAddress((void**)&WfT,  g_WfT);
    cudaGetSymbolAddress((void**)&WzT,  g_WzT);
    cudaGetSymbolAddress((void**)&WrT,  g_WrT);
    cudaGetSymbolAddress((void**)&WtT,  g_WtT);

    // transpose weights once per call
    k_transpose<<<dim3(32, 8), dim3(32, 8)>>>(Wf, WfT, 256, 1024);
    k_transpose<<<dim3(16, 8), dim3(32, 8)>>>(Wz, WzT, 256, 512);
    k_transpose<<<dim3(16, 8), dim3(32, 8)>>>(Wr, WrT, 256, 512);
    k_transpose<<<dim3(16, 8), dim3(32, 8)>>>(Wt, WtT, 256, 512);

    const long long sNF = (long long)NN * HH;
    const long long sEH = (long long)EE * HH;
    const long long sPQ = (long long)EE * NN;
    const int TOT = BB * NN * HH;
    const int MR = BB * NN;

    const float* nfIn = node_feature;
    for (int hop = 0; hop < 2; hop++) {
        float* nfOut = (hop == 1) ? out : nf1;

        // tmp1[b,e,h] = sum_n node2edge[b,e,n] * nf[b,n,h]
        rungemm<0, 0, 4>(node2edge, nfIn, tmp1, EE, NN, NN, sPQ, sNF, sEH, BB, nullptr, nullptr, nullptr);
        // tmp2[b,e,h] = sum_n edge2node[b,n,e] * nf[b,n,h]   (A accessed transposed, lda=E)
        rungemm<1, 0, 4>(edge2node, nfIn, tmp2, EE, NN, EE, sPQ, sNF, sEH, BB, nullptr, nullptr, nullptr);
        // bw[b,n,h] = sum_e edge2node[b,n,e] * tmp1[b,e,h]
        rungemm<0, 0, 4>(edge2node, tmp1, bwP, NN, EE, EE, sPQ, sEH, sNF, BB, nullptr, nullptr, nullptr);
        // fw[b,n,h] = sum_e node2edge[b,e,n] * tmp2[b,e,h]   (A transposed, lda=N)
        rungemm<1, 0, 4>(node2edge, tmp2, fwP, NN, EE, NN, sPQ, sEH, sNF, BB, nullptr, nullptr, nullptr);

        // gated fusion
        k_build_cat4<<<TOT / 256, 256>>>(fwP, bwP, cat4, TOT);
        rungemm<0, 2, 1>(cat4, WfT, agg, MR, 4 * HH, 4 * HH, 0, 0, 0, 1, bf, fwP, bwP);

        // GRU step
        k_build_hx<<<TOT / 256, 256>>>(nfIn, agg, hx, TOT);
        rungemm<0, 1, 1>(hx, WzT, zg, MR, 2 * HH, 2 * HH, 0, 0, 0, 1, nullptr, nullptr, nullptr);
        rungemm<0, 1, 1>(hx, WrT, rg, MR, 2 * HH, 2 * HH, 0, 0, 0, 1, nullptr, nullptr, nullptr);
        k_build_cat2<<<TOT / 256, 256>>>(rg, nfIn, agg, cat2, TOT);
        rungemm<0, 3, 1>(cat2, WtT, nfOut, MR, 2 * HH, 2 * HH, 0, 0, 0, 1, nullptr, zg, nfIn);

        nfIn = nfOut;
    }
}

// round 7
// speedup vs baseline: 2.0543x; 1.2869x over previous
#include <cuda_runtime.h>
#include <cstdint>
#include <math.h>

// ---------------- problem constants ----------------
#define BB 8
#define NN 1000
#define EE 4000
#define HH 256

// Big-GEMM tiling: CTA tile 128x128, k-tile 16. Fragment-packed images:
// per (b, mtile, ktile): 4096 floats = [hi 2048][lo 2048] in mma-fragment order.
#define MT12 32      // GEMM1/2: M=4000 -> 32 tiles of 128
#define KT12 63      // K=1000  -> 63 tiles of 16
#define MT34 8       // GEMM3/4: M=1000 -> 8 tiles
#define KT34 250     // K=4000  -> 250 tiles

#define PA12_SZ (MT12*KT12*4096*BB)
#define PA34_SZ (MT34*KT34*4096*BB)
#define PB_NF_SZ (KT12*2*4096*BB)
#define PB_T_SZ  (KT34*2*4096*BB)

// ---------------- scratch (static device globals; no allocation) ----------------
__device__ float g_pA1[PA12_SZ];   // node2edge normal   (M=E,K=N)
__device__ float g_pA2[PA12_SZ];   // edge2node transposed (M=E,K=N)
__device__ float g_pA3[PA34_SZ];   // edge2node normal   (M=N,K=E)
__device__ float g_pA4[PA34_SZ];   // node2edge transposed (M=N,K=E)
__device__ float g_pBnf[PB_NF_SZ];
__device__ float g_pBt1[PB_T_SZ];
__device__ float g_pBt2[PB_T_SZ];

__device__ float g_tmp1[BB*EE*HH];
__device__ float g_tmp2[BB*EE*HH];
__device__ float g_bw  [BB*NN*HH];
__device__ float g_fw  [BB*NN*HH];
__device__ float g_agg [BB*NN*HH];
__device__ float g_zg  [BB*NN*HH];
__device__ float g_rg  [BB*NN*HH];
__device__ float g_nf1 [BB*NN*HH];
__device__ float g_cat4[BB*NN*4*HH];
__device__ float g_hx  [BB*NN*2*HH];
__device__ float g_cat2[BB*NN*2*HH];
__device__ float g_WfT [4*HH*HH];
__device__ float g_WzT [2*HH*HH];
__device__ float g_WrT [2*HH*HH];
__device__ float g_WtT [2*HH*HH];

// ---------------- helpers ----------------
__device__ __forceinline__ uint32_t f2tf(float f) {
    uint32_t u; asm("cvt.rna.tf32.f32 %0, %1;" : "=r"(u) : "f"(f)); return u;
}

__device__ __forceinline__ void split2(float x, float& h, float& l) {
    uint32_t hu = f2tf(x);
    h = __uint_as_float(hu);
    float r1 = __fadd_rn(x, -h);
    uint32_t lu = f2tf(r1);
    l = __uint_as_float(lu);
}

__device__ __forceinline__ void mma8(float* d, const uint32_t* a, uint32_t b0, uint32_t b1) {
    asm volatile(
        "mma.sync.aligned.m16n8k8.row.col.f32.tf32.tf32.f32 "
        "{%0,%1,%2,%3},{%4,%5,%6,%7},{%8,%9},{%0,%1,%2,%3};"
        : "+f"(d[0]), "+f"(d[1]), "+f"(d[2]), "+f"(d[3])
        : "r"(a[0]), "r"(a[1]), "r"(a[2]), "r"(a[3]), "r"(b0), "r"(b1));
}

// fragment offset for A element (mRel in [0,128), kRel in [0,16)) within 2048-float plane
__device__ __forceinline__ int a_frag_off(int mRel, int kRel) {
    int ms = mRel >> 4;
    int ks2 = kRel >> 3;
    int lane = (mRel & 7) * 4 + (kRel & 3);
    int areg = ((kRel >> 2) & 1) * 2 + ((mRel >> 3) & 1);
    return (((ms * 2) + ks2) * 32 + lane) * 4 + areg;
}
// fragment offset for B element (kRel in [0,16), nRel in [0,128))
__device__ __forceinline__ int b_frag_off(int kRel, int nRel) {
    int ns = nRel >> 3;
    int lane = (nRel & 7) * 4 + (kRel & 3);
    int breg = ((kRel >> 3) & 1) * 2 + ((kRel >> 2) & 1);
    return (ns * 32 + lane) * 4 + breg;
}

// ---------------- pack kernels ----------------
template<int TRANSA>
__global__ void __launch_bounds__(256)
k_packA(const float* __restrict__ src, float* __restrict__ dst,
        int M, int K, int lda, long long sSrc, int MT, int KT)
{
    __shared__ float img[4096];
    int kt = blockIdx.x, mt = blockIdx.y, b = blockIdx.z;
    const float* S = src + (long long)b * sSrc;
    int m0 = mt * 128, k0 = kt * 16;
    int tid = threadIdx.x;
#pragma unroll
    for (int it = 0; it < 2; it++) {
        int linear = tid + it * 256;
        float4 v = make_float4(0.f, 0.f, 0.f, 0.f);
        int mR[4], kR[4];
        if (TRANSA == 0) {
            int row = linear >> 2, c4 = (linear & 3) << 2;
            int gm = m0 + row, gk = k0 + c4;
            if (gm < M) {
                if (gk + 3 < K) v = *reinterpret_cast<const float4*>(S + (size_t)gm * lda + gk);
                else {
                    float* p = &v.x;
#pragma unroll
                    for (int j = 0; j < 4; j++) if (gk + j < K) p[j] = S[(size_t)gm * lda + gk + j];
                }
            }
#pragma unroll
            for (int j = 0; j < 4; j++) { mR[j] = row; kR[j] = c4 + j; }
        } else {
            int kk = linear >> 5, m4 = (linear & 31) << 2;
            int gk = k0 + kk, gm = m0 + m4;
            if (gk < K) {
                if (gm + 3 < M) v = *reinterpret_cast<const float4*>(S + (size_t)gk * lda + gm);
                else {
                    float* p = &v.x;
#pragma unroll
                    for (int j = 0; j < 4; j++) if (gm + j < M) p[j] = S[(size_t)gk * lda + gm + j];
                }
            }
#pragma unroll
            for (int j = 0; j < 4; j++) { mR[j] = m4 + j; kR[j] = kk; }
        }
        const float* pv = &v.x;
#pragma unroll
        for (int j = 0; j < 4; j++) {
            float h, l;
            split2(pv[j], h, l);
            int off = a_frag_off(mR[j], kR[j]);
            img[off] = h; img[2048 + off] = l;
        }
    }
    __syncthreads();
    float4* D = reinterpret_cast<float4*>(dst + (((long long)b * MT + mt) * KT + kt) * 4096);
    const float4* I = reinterpret_cast<const float4*>(img);
#pragma unroll
    for (int i = 0; i < 4; i++) D[tid + i * 256] = I[tid + i * 256];
}

__global__ void __launch_bounds__(256)
k_packB(const float* __restrict__ src, float* __restrict__ dst, int K, int KT)
{
    __shared__ float img[4096];
    int kt = blockIdx.x, nt = blockIdx.y, b = blockIdx.z;
    const float* S = src + (long long)b * K * 256;
    int k0 = kt * 16, n0 = nt * 128;
    int tid = threadIdx.x;
#pragma unroll
    for (int it = 0; it < 2; it++) {
        int linear = tid + it * 256;
        int kr = linear >> 5, n4 = (linear & 31) << 2;
        int gk = k0 + kr;
        float4 v = make_float4(0.f, 0.f, 0.f, 0.f);
        if (gk < K) v = *reinterpret_cast<const float4*>(S + (size_t)gk * 256 + n0 + n4);
        const float* pv = &v.x;
#pragma unroll
        for (int j = 0; j < 4; j++) {
            float h, l;
            split2(pv[j], h, l);
            int off = b_frag_off(kr, n4 + j);
            img[off] = h; img[2048 + off] = l;
        }
    }
    __syncthreads();
    float4* D = reinterpret_cast<float4*>(dst + (((long long)b * KT + kt) * 2 + nt) * 4096);
    const float4* I = reinterpret_cast<const float4*>(img);
#pragma unroll
    for (int i = 0; i < 4; i++) D[tid + i * 256] = I[tid + i * 256];
}

// ---------------- fragment GEMM (big GEMMs, MODE 0 only) ----------------
__global__ void __launch_bounds__(256)
gemm_frag(const float* __restrict__ pA, const float* __restrict__ pB, float* __restrict__ C,
          int M, int MT, int KT)
{
    extern __shared__ float sm[];   // 2 buffers x (A 4096 + B 4096) floats = 64KB
    const int tid = threadIdx.x;
    const int nt = blockIdx.x, mt = blockIdx.y, b = blockIdx.z;
    const float4* Abase = reinterpret_cast<const float4*>(pA) + ((long long)b * MT + mt) * KT * 1024;
    const float4* Bbase = reinterpret_cast<const float4*>(pB) + (long long)b * KT * 2048;

    const int lane = tid & 31, warp = tid >> 5;
    const int wm = warp >> 2, wn = warp & 3;
    const int gid = lane >> 2, tig = lane & 3;

    float acc[64], mst[64];
#pragma unroll
    for (int i = 0; i < 64; i++) { acc[i] = 0.f; mst[i] = 0.f; }

    float4 stage[8];
    auto ldg = [&](int kt) {
        const float4* A = Abase + (size_t)kt * 1024;
        const float4* Bt = Bbase + ((size_t)kt * 2 + nt) * 1024;
#pragma unroll
        for (int i = 0; i < 4; i++) stage[i] = A[tid + i * 256];
#pragma unroll
        for (int i = 0; i < 4; i++) stage[4 + i] = Bt[tid + i * 256];
    };
    auto sts = [&](int buf) {
        float4* s = reinterpret_cast<float4*>(sm + buf * 8192);
#pragma unroll
        for (int i = 0; i < 4; i++) s[tid + i * 256] = stage[i];
#pragma unroll
        for (int i = 0; i < 4; i++) s[1024 + tid + i * 256] = stage[4 + i];
    };
    auto compute = [&](int buf) {
        const float* sA = sm + buf * 8192;
        const float* sB = sm + buf * 8192 + 4096;
        float4 bh[4], bl[4];
#pragma unroll
        for (int ni = 0; ni < 4; ni++) {
            int ns = wn * 4 + ni;
            bh[ni] = *reinterpret_cast<const float4*>(sB + (ns * 32 + lane) * 4);
            bl[ni] = *reinterpret_cast<const float4*>(sB + 2048 + (ns * 32 + lane) * 4);
        }
#pragma unroll
        for (int ks = 0; ks < 2; ks++) {
#pragma unroll
            for (int mi = 0; mi < 4; mi++) {
                int ms = wm * 4 + mi;
                float4 a4h = *reinterpret_cast<const float4*>(sA + ((ms * 2 + ks) * 32 + lane) * 4);
                float4 a4l = *reinterpret_cast<const float4*>(sA + 2048 + ((ms * 2 + ks) * 32 + lane) * 4);
                uint32_t ah[4] = {__float_as_uint(a4h.x), __float_as_uint(a4h.y),
                                  __float_as_uint(a4h.z), __float_as_uint(a4h.w)};
                uint32_t al[4] = {__float_as_uint(a4l.x), __float_as_uint(a4l.y),
                                  __float_as_uint(a4l.z), __float_as_uint(a4l.w)};
#pragma unroll
                for (int ni = 0; ni < 4; ni++) {
                    float* a4 = &acc[(mi * 4 + ni) * 4];
                    uint32_t bhk0 = (ks == 0) ? __float_as_uint(bh[ni].x) : __float_as_uint(bh[ni].z);
                    uint32_t bhk1 = (ks == 0) ? __float_as_uint(bh[ni].y) : __float_as_uint(bh[ni].w);
                    uint32_t blk0 = (ks == 0) ? __float_as_uint(bl[ni].x) : __float_as_uint(bl[ni].z);
                    uint32_t blk1 = (ks == 0) ? __float_as_uint(bl[ni].y) : __float_as_uint(bl[ni].w);
                    mma8(a4, al, bhk0, bhk1);
                    mma8(a4, ah, blk0, blk1);
                    mma8(a4, ah, bhk0, bhk1);
                }
            }
        }
    };

    ldg(0);
    sts(0);
    __syncthreads();
    for (int kt = 0; kt < KT; kt++) {
        if (kt + 1 < KT) ldg(kt + 1);
        compute(kt & 1);
        if (((kt + 1) & 3) == 0 || kt == KT - 1) {
#pragma unroll
            for (int i = 0; i < 64; i++) { mst[i] = __fadd_rn(mst[i], acc[i]); acc[i] = 0.f; }
        }
        if (kt + 1 < KT) sts((kt + 1) & 1);
        __syncthreads();
    }

    float* Cb = C + (long long)b * M * 256;
#pragma unroll
    for (int mi = 0; mi < 4; mi++) {
#pragma unroll
        for (int ni = 0; ni < 4; ni++) {
            int rB = mt * 128 + wm * 64 + mi * 16 + gid;
            int cB = nt * 128 + wn * 32 + ni * 8 + tig * 2;
#pragma unroll
            for (int rr = 0; rr < 2; rr++) {
                int r = rB + rr * 8;
                if (r < M) {
                    Cb[(size_t)r * 256 + cB]     = mst[(mi * 4 + ni) * 4 + rr * 2 + 0];
                    Cb[(size_t)r * 256 + cB + 1] = mst[(mi * 4 + ni) * 4 + rr * 2 + 1];
                }
            }
        }
    }
}

// ---------------- small-GEMM kernel (R4 path with FOLD=1; MODEs 1,2,3) ----------------
#define TBM 128
#define TBN 128
#define TBK 16
#define ASTR 20
#define BSTR 136
#define A_BUF (TBM*ASTR)
#define B_BUF (TBK*BSTR)
#define SMEM_FLOATS (4*A_BUF + 4*B_BUF)
#define SMEM_BYTES (SMEM_FLOATS * 4)

__device__ __forceinline__ void mma8v(float* d, const uint32_t* a, const uint32_t* b) {
    asm volatile(
        "mma.sync.aligned.m16n8k8.row.col.f32.tf32.tf32.f32 "
        "{%0,%1,%2,%3},{%4,%5,%6,%7},{%8,%9},{%0,%1,%2,%3};"
        : "+f"(d[0]), "+f"(d[1]), "+f"(d[2]), "+f"(d[3])
        : "r"(a[0]), "r"(a[1]), "r"(a[2]), "r"(a[3]), "r"(b[0]), "r"(b[1]));
}

template<int MODE>
__global__ void __launch_bounds__(256)
gemm_k(const float* __restrict__ A, const float* __restrict__ B, float* __restrict__ C,
       int M, int K,
       const float* __restrict__ bias,
       const float* __restrict__ aux1, const float* __restrict__ aux2)
{
    extern __shared__ float sm[];
    float* sAh = sm;
    float* sAl = sm + 2*A_BUF;
    float* sBh = sm + 4*A_BUF;
    float* sBl = sm + 4*A_BUF + 2*B_BUF;

    const int tid = threadIdx.x;
    const int m0 = blockIdx.y * TBM;
    const int n0 = blockIdx.x * TBN;
    const int lda = K;

    const int lane = tid & 31, warp = tid >> 5;
    const int wm = warp >> 2, wn = warp & 3;
    const int gid = lane >> 2, tig = lane & 3;

    float acc[64], mst[64];
#pragma unroll
    for (int i = 0; i < 64; i++) { acc[i] = 0.f; mst[i] = 0.f; }

    const int KT = (K + TBK - 1) / TBK;
    float aR[8], bR[8];

    auto loadTiles = [&](int k0) {
#pragma unroll
        for (int it = 0; it < 2; it++) {
            int linear = tid + it * 256;
            float4 v = make_float4(0.f, 0.f, 0.f, 0.f);
            int row = linear >> 2, c4 = (linear & 3) << 2;
            int gr = m0 + row, gc = k0 + c4;
            if (gr < M && gc + 3 < K)
                v = *reinterpret_cast<const float4*>(A + (size_t)gr * lda + gc);
            aR[it*4+0] = v.x; aR[it*4+1] = v.y; aR[it*4+2] = v.z; aR[it*4+3] = v.w;

            int kr = linear >> 5, n4 = (linear & 31) << 2;
            int gk2 = k0 + kr;
            float4 w = make_float4(0.f, 0.f, 0.f, 0.f);
            if (gk2 < K)
                w = *reinterpret_cast<const float4*>(B + (size_t)gk2 * 256 + n0 + n4);
            bR[it*4+0] = w.x; bR[it*4+1] = w.y; bR[it*4+2] = w.z; bR[it*4+3] = w.w;
        }
    };

    auto storeTiles = [&](int buf) {
        float* ah = sAh + buf * A_BUF; float* al = sAl + buf * A_BUF;
        float* bh = sBh + buf * B_BUF; float* bl = sBl + buf * B_BUF;
#pragma unroll
        for (int it = 0; it < 2; it++) {
            int linear = tid + it * 256;
#pragma unroll
            for (int j = 0; j < 4; j++) {
                float h, l;
                split2(aR[it*4+j], h, l);
                int row = linear >> 2, c4 = (linear & 3) << 2;
                int idx = row*ASTR + c4 + j;
                ah[idx] = h; al[idx] = l;

                split2(bR[it*4+j], h, l);
                int kr = linear >> 5, n4 = (linear & 31) << 2;
                int bidx = kr * BSTR + n4 + j;
                bh[bidx] = h; bl[bidx] = l;
            }
        }
    };

    auto computeTile = [&](int buf) {
        const float* Ah = sAh + buf * A_BUF; const float* Al = sAl + buf * A_BUF;
        const float* Bh = sBh + buf * B_BUF; const float* Bl = sBl + buf * B_BUF;
#pragma unroll
        for (int ks = 0; ks < 2; ks++) {
            int kb = ks * 8;
            uint32_t bh[4][2], bl[4][2];
#pragma unroll
            for (int ni = 0; ni < 4; ni++) {
                int cc = wn * 32 + ni * 8 + gid;
                bh[ni][0] = __float_as_uint(Bh[(kb+tig)  *BSTR + cc]);
                bh[ni][1] = __float_as_uint(Bh[(kb+tig+4)*BSTR + cc]);
                bl[ni][0] = __float_as_uint(Bl[(kb+tig)  *BSTR + cc]);
                bl[ni][1] = __float_as_uint(Bl[(kb+tig+4)*BSTR + cc]);
            }
#pragma unroll
            for (int mi = 0; mi < 4; mi++) {
                int r0 = wm * 64 + mi * 16 + gid;
                uint32_t ah[4], al[4];
#pragma unroll
                for (int q = 0; q < 4; q++) {
                    int rr = r0 + ((q & 1) ? 8 : 0);
                    int kk = kb + tig + ((q & 2) ? 4 : 0);
                    ah[q] = __float_as_uint(Ah[rr*ASTR + kk]);
                    al[q] = __float_as_uint(Al[rr*ASTR + kk]);
                }
#pragma unroll
                for (int ni = 0; ni < 4; ni++) {
                    float* a4 = &acc[(mi*4 + ni)*4];
                    mma8v(a4, al, bh[ni]);
                    mma8v(a4, ah, bl[ni]);
                    mma8v(a4, ah, bh[ni]);
                }
            }
        }
    };

    loadTiles(0);
    storeTiles(0);
    __syncthreads();
    for (int kt = 0; kt < KT; kt++) {
        if (kt + 1 < KT) loadTiles((kt + 1) * TBK);
        computeTile(kt & 1);
        // FOLD=1: fold fresh chunk into master after EVERY k-tile (precision-critical:
        // removing this was the R6 regression)
#pragma unroll
        for (int i = 0; i < 64; i++) { mst[i] = __fadd_rn(mst[i], acc[i]); acc[i] = 0.f; }
        if (kt + 1 < KT) storeTiles((kt + 1) & 1);
        __syncthreads();
    }

#pragma unroll
    for (int mi = 0; mi < 4; mi++) {
#pragma unroll
        for (int ni = 0; ni < 4; ni++) {
            int rB = m0 + wm * 64 + mi * 16 + gid;
            int cB = n0 + wn * 32 + ni * 8 + tig * 2;
#pragma unroll
            for (int rr = 0; rr < 2; rr++) {
                int r = rB + rr * 8;
                if (r < M) {
#pragma unroll
                    for (int c2 = 0; c2 < 2; c2++) {
                        int c = cB + c2;
                        float v = mst[(mi*4 + ni)*4 + rr * 2 + c2];
                        size_t idx = (size_t)r * 256 + c;
                        if (MODE == 1) {
                            C[idx] = 1.f / (1.f + expf(-v));
                        } else if (MODE == 2) {
                            float z = 1.f / (1.f + expf(-(v + bias[c])));
                            C[idx] = (1.f - z) * aux1[idx] + z * aux2[idx];
                        } else {
                            float t = tanhf(v);
                            float z = aux1[idx];
                            C[idx] = (1.f - z) * aux2[idx] + z * t;
                        }
                    }
                }
            }
        }
    }
}

// ---------------- elementwise kernels ----------------
__global__ void k_build_cat4(const float* __restrict__ fw, const float* __restrict__ bw,
                             float* __restrict__ cat, int total) {
    int i = blockIdx.x * blockDim.x + threadIdx.x;
    if (i >= total) return;
    int row = i >> 8, h = i & 255;
    float f = fw[i], b = bw[i];
    float* c = cat + ((size_t)row << 10) + h;
    c[0] = f; c[256] = b; c[512] = f * b; c[768] = f - b;
}

__global__ void k_build_hx(const float* __restrict__ nf, const float* __restrict__ agg,
                           float* __restrict__ hx, int total) {
    int i = blockIdx.x * blockDim.x + threadIdx.x;
    if (i >= total) return;
    int row = i >> 8, h = i & 255;
    float* p = hx + ((size_t)row << 9) + h;
    p[0] = nf[i]; p[256] = agg[i];
}

__global__ void k_build_cat2(const float* __restrict__ rg, const float* __restrict__ nf,
                             const float* __restrict__ agg, float* __restrict__ c2, int total) {
    int i = blockIdx.x * blockDim.x + threadIdx.x;
    if (i >= total) return;
    int row = i >> 8, h = i & 255;
    float* p = c2 + ((size_t)row << 9) + h;
    p[0] = rg[i] * nf[i]; p[256] = agg[i];
}

__global__ void k_transpose(const float* __restrict__ src, float* __restrict__ dst, int R, int C) {
    __shared__ float t[32][33];
    int bx = blockIdx.x * 32, by = blockIdx.y * 32;
    int x = threadIdx.x, y = threadIdx.y;
#pragma unroll
    for (int j = 0; j < 32; j += 8) {
        int r = by + y + j, c = bx + x;
        if (r < R && c < C) t[y + j][x] = src[(size_t)r * C + c];
    }
    __syncthreads();
#pragma unroll
    for (int j = 0; j < 32; j += 8) {
        int r = bx + y + j, c = by + x;
        if (r < C && c < R) dst[(size_t)r * R + c] = t[x][y + j];
    }
}

// ---------------- host side ----------------
#define FRAG_SMEM (2*8192*4)   // 65536 bytes

static void run_frag(const float* pA, const float* pB, float* C, int M, int MT, int KT)
{
    cudaFuncSetAttribute(gemm_frag, cudaFuncAttributeMaxDynamicSharedMemorySize, FRAG_SMEM);
    dim3 grid(2, MT, BB);
    gemm_frag<<<grid, 256, FRAG_SMEM>>>(pA, pB, C, M, MT, KT);
}

template<int MODE>
static void run_small(const float* A, const float* B, float* C, int M, int K,
                      const float* bias, const float* a1, const float* a2)
{
    cudaFuncSetAttribute(gemm_k<MODE>, cudaFuncAttributeMaxDynamicSharedMemorySize, SMEM_BYTES);
    dim3 grid(2, (M + TBM - 1) / TBM, 1);
    gemm_k<MODE><<<grid, 256, SMEM_BYTES>>>(A, B, C, M, K, bias, a1, a2);
}

extern "C" void kernel_launch(void* const* d_in, const int* in_sizes, int n_in,
                              void* d_out, int out_size)
{
    const float* node_feature = (const float*)d_in[0];
    const float* node2edge    = (const float*)d_in[1];
    const float* edge2node    = (const float*)d_in[2];
    const float* Wz = (const float*)d_in[3];
    const float* Wr = (const float*)d_in[4];
    const float* Wt = (const float*)d_in[5];
    const float* Wf = (const float*)d_in[6];
    const float* bf = (const float*)d_in[7];
    float* out = (float*)d_out;

    float *pA1, *pA2, *pA3, *pA4, *pBnf, *pBt1, *pBt2;
    float *tmp1, *tmp2, *bwP, *fwP, *agg, *zg, *rg, *nf1, *cat4, *hx, *cat2;
    float *WfT, *WzT, *WrT, *WtT;
    cudaGetSymbolAddress((void**)&pA1, g_pA1);
    cudaGetSymbolAddress((void**)&pA2, g_pA2);
    cudaGetSymbolAddress((void**)&pA3, g_pA3);
    cudaGetSymbolAddress((void**)&pA4, g_pA4);
    cudaGetSymbolAddress((void**)&pBnf, g_pBnf);
    cudaGetSymbolAddress((void**)&pBt1, g_pBt1);
    cudaGetSymbolAddress((void**)&pBt2, g_pBt2);
    cudaGetSymbolAddress((void**)&tmp1, g_tmp1);
    cudaGetSymbolAddress((void**)&tmp2, g_tmp2);
    cudaGetSymbolAddress((void**)&bwP,  g_bw);
    cudaGetSymbolAddress((void**)&fwP,  g_fw);
    cudaGetSymbolAddress((void**)&agg,  g_agg);
    cudaGetSymbolAddress((void**)&zg,   g_zg);
    cudaGetSymbolAddress((void**)&rg,   g_rg);
    cudaGetSymbolAddress((void**)&nf1,  g_nf1);
    cudaGetSymbolAddress((void**)&cat4, g_cat4);
    cudaGetSymbolAddress((void**)&hx,   g_hx);
    cudaGetSymbolAddress((void**)&cat2, g_cat2);
    cudaGetSymbolAddress((void**)&WfT,  g_WfT);
    cudaGetSymbolAddress((void**)&WzT,  g_WzT);
    cudaGetSymbolAddress((void**)&WrT,  g_WrT);
    cudaGetSymbolAddress((void**)&WtT,  g_WtT);

    // weights transpose
    k_transpose<<<dim3(32, 8), dim3(32, 8)>>>(Wf, WfT, 256, 1024);
    k_transpose<<<dim3(16, 8), dim3(32, 8)>>>(Wz, WzT, 256, 512);
    k_transpose<<<dim3(16, 8), dim3(32, 8)>>>(Wr, WrT, 256, 512);
    k_transpose<<<dim3(16, 8), dim3(32, 8)>>>(Wt, WtT, 256, 512);

    const long long sPQ = (long long)EE * NN;
    const int TOT = BB * NN * HH;
    const int MR = BB * NN;

    // pack adjacency fragment images (reused both hops)
    k_packA<0><<<dim3(KT12, MT12, BB), 256>>>(node2edge, pA1, EE, NN, NN, sPQ, MT12, KT12);
    k_packA<1><<<dim3(KT12, MT12, BB), 256>>>(edge2node, pA2, EE, NN, EE, sPQ, MT12, KT12);
    k_packA<0><<<dim3(KT34, MT34, BB), 256>>>(edge2node, pA3, NN, EE, EE, sPQ, MT34, KT34);
    k_packA<1><<<dim3(KT34, MT34, BB), 256>>>(node2edge, pA4, NN, EE, NN, sPQ, MT34, KT34);

    const float* nfIn = node_feature;
    for (int hop = 0; hop < 2; hop++) {
        float* nfOut = (hop == 1) ? out : nf1;

        // pack nf as B image
        k_packB<<<dim3(KT12, 2, BB), 256>>>(nfIn, pBnf, NN, KT12);

        // tmp1 = node2edge @ nf ; tmp2 = edge2node^T @ nf
        run_frag(pA1, pBnf, tmp1, EE, MT12, KT12);
        run_frag(pA2, pBnf, tmp2, EE, MT12, KT12);

        // pack tmp1/tmp2 as B images
        k_packB<<<dim3(KT34, 2, BB), 256>>>(tmp1, pBt1, EE, KT34);
        k_packB<<<dim3(KT34, 2, BB), 256>>>(tmp2, pBt2, EE, KT34);

        // bw = edge2node @ tmp1 ; fw = node2edge^T @ tmp2
        run_frag(pA3, pBt1, bwP, NN, MT34, KT34);
        run_frag(pA4, pBt2, fwP, NN, MT34, KT34);

        // gated fusion
        k_build_cat4<<<TOT / 256, 256>>>(fwP, bwP, cat4, TOT);
        run_small<2>(cat4, WfT, agg, MR, 4 * HH, bf, fwP, bwP);

        // GRU step
        k_build_hx<<<TOT / 256, 256>>>(nfIn, agg, hx, TOT);
        run_small<1>(hx, WzT, zg, MR, 2 * HH, nullptr, nullptr, nullptr);
        run_small<1>(hx, WrT, rg, MR, 2 * HH, nullptr, nullptr, nullptr);
        k_build_cat2<<<TOT / 256, 256>>>(rg, nfIn, agg, cat2, TOT);
        run_small<3>(cat2, WtT, nfOut, MR, 2 * HH, nullptr, zg, nfIn);

        nfIn = nfOut;
    }
}

// round 8
// speedup vs baseline: 2.2566x; 1.0985x over previous
#include <cuda_runtime.h>
#include <cstdint>
#include <math.h>

// ---------------- problem constants ----------------
#define BB 8
#define NN 1000
#define EE 4000
#define HH 256

// Big-GEMM tiling: CTA tile 128x128, k-tile 16. Fragment-packed images:
// per (b, mtile, ktile): 4096 floats = [hi 2048][lo 2048] in mma-fragment order.
#define MT12 32      // GEMM1/2: M=4000 -> 32 tiles of 128
#define KT12 63      // K=1000  -> 63 tiles of 16
#define MT34 8       // GEMM3/4: M=1000 -> 8 tiles
#define KT34 250     // K=4000  -> 250 tiles

#define PA12_SZ (MT12*KT12*4096*BB)
#define PA34_SZ (MT34*KT34*4096*BB)
#define PB_NF_SZ (KT12*2*4096*BB)
#define PB_T_SZ  (KT34*2*4096*BB)

// ---------------- scratch (static device globals; no allocation) ----------------
__device__ float g_pA1[PA12_SZ];   // node2edge normal   (M=E,K=N)
__device__ float g_pA2[PA12_SZ];   // edge2node transposed (M=E,K=N)
__device__ float g_pA3[PA34_SZ];   // edge2node normal   (M=N,K=E)
__device__ float g_pA4[PA34_SZ];   // node2edge transposed (M=N,K=E)
__device__ float g_pBnf[PB_NF_SZ];
__device__ float g_pBt1[PB_T_SZ];
__device__ float g_pBt2[PB_T_SZ];

__device__ float g_tmp1[BB*EE*HH];
__device__ float g_tmp2[BB*EE*HH];
__device__ float g_bw  [BB*NN*HH];
__device__ float g_fw  [BB*NN*HH];
__device__ float g_agg [BB*NN*HH];
__device__ float g_zg  [BB*NN*HH];
__device__ float g_rg  [BB*NN*HH];
__device__ float g_nf1 [BB*NN*HH];
__device__ float g_cat4[BB*NN*4*HH];
__device__ float g_hx  [BB*NN*2*HH];
__device__ float g_cat2[BB*NN*2*HH];
__device__ float g_WfT [4*HH*HH];
__device__ float g_WzT [2*HH*HH];
__device__ float g_WrT [2*HH*HH];
__device__ float g_WtT [2*HH*HH];

// ---------------- helpers ----------------
__device__ __forceinline__ uint32_t f2tf(float f) {
    uint32_t u; asm("cvt.rna.tf32.f32 %0, %1;" : "=r"(u) : "f"(f)); return u;
}

__device__ __forceinline__ void split2(float x, float& h, float& l) {
    uint32_t hu = f2tf(x);
    h = __uint_as_float(hu);
    float r1 = __fadd_rn(x, -h);
    uint32_t lu = f2tf(r1);
    l = __uint_as_float(lu);
}

__device__ __forceinline__ void mma8(float* d, const uint32_t* a, uint32_t b0, uint32_t b1) {
    asm volatile(
        "mma.sync.aligned.m16n8k8.row.col.f32.tf32.tf32.f32 "
        "{%0,%1,%2,%3},{%4,%5,%6,%7},{%8,%9},{%0,%1,%2,%3};"
        : "+f"(d[0]), "+f"(d[1]), "+f"(d[2]), "+f"(d[3])
        : "r"(a[0]), "r"(a[1]), "r"(a[2]), "r"(a[3]), "r"(b0), "r"(b1));
}

__device__ __forceinline__ void cp_async16(float4* smem_ptr, const float4* gptr) {
    uint32_t s = (uint32_t)__cvta_generic_to_shared(smem_ptr);
    asm volatile("cp.async.cg.shared.global [%0], [%1], 16;" :: "r"(s), "l"(gptr));
}
__device__ __forceinline__ void cp_commit() {
    asm volatile("cp.async.commit_group;");
}
template<int N>
__device__ __forceinline__ void cp_wait() {
    asm volatile("cp.async.wait_group %0;" :: "n"(N));
}

// fragment offset for A element (mRel in [0,128), kRel in [0,16)) within 2048-float plane
__device__ __forceinline__ int a_frag_off(int mRel, int kRel) {
    int ms = mRel >> 4;
    int ks2 = kRel >> 3;
    int lane = (mRel & 7) * 4 + (kRel & 3);
    int areg = ((kRel >> 2) & 1) * 2 + ((mRel >> 3) & 1);
    return (((ms * 2) + ks2) * 32 + lane) * 4 + areg;
}
// fragment offset for B element (kRel in [0,16), nRel in [0,128))
__device__ __forceinline__ int b_frag_off(int kRel, int nRel) {
    int ns = nRel >> 3;
    int lane = (nRel & 7) * 4 + (kRel & 3);
    int breg = ((kRel >> 3) & 1) * 2 + ((kRel >> 2) & 1);
    return (ns * 32 + lane) * 4 + breg;
}

// ---------------- pack kernels ----------------
template<int TRANSA>
__global__ void __launch_bounds__(256)
k_packA(const float* __restrict__ src, float* __restrict__ dst,
        int M, int K, int lda, long long sSrc, int MT, int KT)
{
    __shared__ float img[4096];
    int kt = blockIdx.x, mt = blockIdx.y, b = blockIdx.z;
    const float* S = src + (long long)b * sSrc;
    int m0 = mt * 128, k0 = kt * 16;
    int tid = threadIdx.x;
#pragma unroll
    for (int it = 0; it < 2; it++) {
        int linear = tid + it * 256;
        float4 v = make_float4(0.f, 0.f, 0.f, 0.f);
        int mR[4], kR[4];
        if (TRANSA == 0) {
            int row = linear >> 2, c4 = (linear & 3) << 2;
            int gm = m0 + row, gk = k0 + c4;
            if (gm < M) {
                if (gk + 3 < K) v = *reinterpret_cast<const float4*>(S + (size_t)gm * lda + gk);
                else {
                    float* p = &v.x;
#pragma unroll
                    for (int j = 0; j < 4; j++) if (gk + j < K) p[j] = S[(size_t)gm * lda + gk + j];
                }
            }
#pragma unroll
            for (int j = 0; j < 4; j++) { mR[j] = row; kR[j] = c4 + j; }
        } else {
            int kk = linear >> 5, m4 = (linear & 31) << 2;
            int gk = k0 + kk, gm = m0 + m4;
            if (gk < K) {
                if (gm + 3 < M) v = *reinterpret_cast<const float4*>(S + (size_t)gk * lda + gm);
                else {
                    float* p = &v.x;
#pragma unroll
                    for (int j = 0; j < 4; j++) if (gm + j < M) p[j] = S[(size_t)gk * lda + gm + j];
                }
            }
#pragma unroll
            for (int j = 0; j < 4; j++) { mR[j] = m4 + j; kR[j] = kk; }
        }
        const float* pv = &v.x;
#pragma unroll
        for (int j = 0; j < 4; j++) {
            float h, l;
            split2(pv[j], h, l);
            int off = a_frag_off(mR[j], kR[j]);
            img[off] = h; img[2048 + off] = l;
        }
    }
    __syncthreads();
    float4* D = reinterpret_cast<float4*>(dst + (((long long)b * MT + mt) * KT + kt) * 4096);
    const float4* I = reinterpret_cast<const float4*>(img);
#pragma unroll
    for (int i = 0; i < 4; i++) D[tid + i * 256] = I[tid + i * 256];
}

__global__ void __launch_bounds__(256)
k_packB(const float* __restrict__ src, float* __restrict__ dst, int K, int KT)
{
    __shared__ float img[4096];
    int kt = blockIdx.x, nt = blockIdx.y, b = blockIdx.z;
    const float* S = src + (long long)b * K * 256;
    int k0 = kt * 16, n0 = nt * 128;
    int tid = threadIdx.x;
#pragma unroll
    for (int it = 0; it < 2; it++) {
        int linear = tid + it * 256;
        int kr = linear >> 5, n4 = (linear & 31) << 2;
        int gk = k0 + kr;
        float4 v = make_float4(0.f, 0.f, 0.f, 0.f);
        if (gk < K) v = *reinterpret_cast<const float4*>(S + (size_t)gk * 256 + n0 + n4);
        const float* pv = &v.x;
#pragma unroll
        for (int j = 0; j < 4; j++) {
            float h, l;
            split2(pv[j], h, l);
            int off = b_frag_off(kr, n4 + j);
            img[off] = h; img[2048 + off] = l;
        }
    }
    __syncthreads();
    float4* D = reinterpret_cast<float4*>(dst + (((long long)b * KT + kt) * 2 + nt) * 4096);
    const float4* I = reinterpret_cast<const float4*>(img);
#pragma unroll
    for (int i = 0; i < 4; i++) D[tid + i * 256] = I[tid + i * 256];
}

// ---------------- fragment GEMM with 4-stage cp.async pipeline ----------------
#define STAGES 4
#define FRAG_SMEM (STAGES*8192*4)   // 131072 bytes

__global__ void __launch_bounds__(256)
gemm_frag(const float* __restrict__ pA, const float* __restrict__ pB, float* __restrict__ C,
          int M, int MT, int KT)
{
    extern __shared__ float sm[];   // STAGES x (A 4096 + B 4096) floats
    const int tid = threadIdx.x;
    const int nt = blockIdx.x, mt = blockIdx.y, b = blockIdx.z;
    const float4* Abase = reinterpret_cast<const float4*>(pA) + ((long long)b * MT + mt) * KT * 1024;
    const float4* Bbase = reinterpret_cast<const float4*>(pB) + (long long)b * KT * 2048;

    const int lane = tid & 31, warp = tid >> 5;
    const int wm = warp >> 2, wn = warp & 3;
    const int gid = lane >> 2, tig = lane & 3;

    float acc[64], mst[64];
#pragma unroll
    for (int i = 0; i < 64; i++) { acc[i] = 0.f; mst[i] = 0.f; }

    auto issue = [&](int kt) {
        float4* s = reinterpret_cast<float4*>(sm + (kt % STAGES) * 8192);
        const float4* A = Abase + (size_t)kt * 1024;
        const float4* Bt = Bbase + ((size_t)kt * 2 + nt) * 1024;
#pragma unroll
        for (int i = 0; i < 4; i++) cp_async16(s + tid + i * 256, A + tid + i * 256);
#pragma unroll
        for (int i = 0; i < 4; i++) cp_async16(s + 1024 + tid + i * 256, Bt + tid + i * 256);
    };

    auto compute = [&](int stage) {
        const float* sA = sm + stage * 8192;
        const float* sB = sm + stage * 8192 + 4096;
        float4 bh[4], bl[4];
#pragma unroll
        for (int ni = 0; ni < 4; ni++) {
            int ns = wn * 4 + ni;
            bh[ni] = *reinterpret_cast<const float4*>(sB + (ns * 32 + lane) * 4);
            bl[ni] = *reinterpret_cast<const float4*>(sB + 2048 + (ns * 32 + lane) * 4);
        }
#pragma unroll
        for (int ks = 0; ks < 2; ks++) {
#pragma unroll
            for (int mi = 0; mi < 4; mi++) {
                int ms = wm * 4 + mi;
                float4 a4h = *reinterpret_cast<const float4*>(sA + ((ms * 2 + ks) * 32 + lane) * 4);
                float4 a4l = *reinterpret_cast<const float4*>(sA + 2048 + ((ms * 2 + ks) * 32 + lane) * 4);
                uint32_t ah[4] = {__float_as_uint(a4h.x), __float_as_uint(a4h.y),
                                  __float_as_uint(a4h.z), __float_as_uint(a4h.w)};
                uint32_t al[4] = {__float_as_uint(a4l.x), __float_as_uint(a4l.y),
                                  __float_as_uint(a4l.z), __float_as_uint(a4l.w)};
#pragma unroll
                for (int ni = 0; ni < 4; ni++) {
                    float* a4 = &acc[(mi * 4 + ni) * 4];
                    uint32_t bhk0 = (ks == 0) ? __float_as_uint(bh[ni].x) : __float_as_uint(bh[ni].z);
                    uint32_t bhk1 = (ks == 0) ? __float_as_uint(bh[ni].y) : __float_as_uint(bh[ni].w);
                    uint32_t blk0 = (ks == 0) ? __float_as_uint(bl[ni].x) : __float_as_uint(bl[ni].z);
                    uint32_t blk1 = (ks == 0) ? __float_as_uint(bl[ni].y) : __float_as_uint(bl[ni].w);
                    mma8(a4, al, bhk0, bhk1);
                    mma8(a4, ah, blk0, blk1);
                    mma8(a4, ah, bhk0, bhk1);
                }
            }
        }
    };

    // prologue: fill STAGES-1 stages
    const int PRE = STAGES - 1;
#pragma unroll
    for (int s = 0; s < PRE; s++) {
        if (s < KT) issue(s);
        cp_commit();
    }

    for (int kt = 0; kt < KT; kt++) {
        cp_wait<STAGES - 2>();      // stage kt complete (<= STAGES-2 groups pending)
        __syncthreads();            // all threads' copies visible to all; prior compute done
        compute(kt % STAGES);
        if (((kt + 1) & 3) == 0 || kt == KT - 1) {
#pragma unroll
            for (int i = 0; i < 64; i++) { mst[i] = __fadd_rn(mst[i], acc[i]); acc[i] = 0.f; }
        }
        if (kt + PRE < KT) issue(kt + PRE);
        cp_commit();                // always commit to keep group accounting uniform
    }

    float* Cb = C + (long long)b * M * 256;
#pragma unroll
    for (int mi = 0; mi < 4; mi++) {
#pragma unroll
        for (int ni = 0; ni < 4; ni++) {
            int rB = mt * 128 + wm * 64 + mi * 16 + gid;
            int cB = nt * 128 + wn * 32 + ni * 8 + tig * 2;
#pragma unroll
            for (int rr = 0; rr < 2; rr++) {
                int r = rB + rr * 8;
                if (r < M) {
                    Cb[(size_t)r * 256 + cB]     = mst[(mi * 4 + ni) * 4 + rr * 2 + 0];
                    Cb[(size_t)r * 256 + cB + 1] = mst[(mi * 4 + ni) * 4 + rr * 2 + 1];
                }
            }
        }
    }
}

// ---------------- small-GEMM kernel (FOLD=1; MODEs 1,2,3) ----------------
#define TBM 128
#define TBN 128
#define TBK 16
#define ASTR 20
#define BSTR 136
#define A_BUF (TBM*ASTR)
#define B_BUF (TBK*BSTR)
#define SMEM_FLOATS (4*A_BUF + 4*B_BUF)
#define SMEM_BYTES (SMEM_FLOATS * 4)

__device__ __forceinline__ void mma8v(float* d, const uint32_t* a, const uint32_t* b) {
    asm volatile(
        "mma.sync.aligned.m16n8k8.row.col.f32.tf32.tf32.f32 "
        "{%0,%1,%2,%3},{%4,%5,%6,%7},{%8,%9},{%0,%1,%2,%3};"
        : "+f"(d[0]), "+f"(d[1]), "+f"(d[2]), "+f"(d[3])
        : "r"(a[0]), "r"(a[1]), "r"(a[2]), "r"(a[3]), "r"(b[0]), "r"(b[1]));
}

template<int MODE>
__global__ void __launch_bounds__(256)
gemm_k(const float* __restrict__ A, const float* __restrict__ B, float* __restrict__ C,
       int M, int K,
       const float* __restrict__ bias,
       const float* __restrict__ aux1, const float* __restrict__ aux2)
{
    extern __shared__ float sm[];
    float* sAh = sm;
    float* sAl = sm + 2*A_BUF;
    float* sBh = sm + 4*A_BUF;
    float* sBl = sm + 4*A_BUF + 2*B_BUF;

    const int tid = threadIdx.x;
    const int m0 = blockIdx.y * TBM;
    const int n0 = blockIdx.x * TBN;
    const int lda = K;

    const int lane = tid & 31, warp = tid >> 5;
    const int wm = warp >> 2, wn = warp & 3;
    const int gid = lane >> 2, tig = lane & 3;

    float acc[64], mst[64];
#pragma unroll
    for (int i = 0; i < 64; i++) { acc[i] = 0.f; mst[i] = 0.f; }

    const int KT = (K + TBK - 1) / TBK;
    float aR[8], bR[8];

    auto loadTiles = [&](int k0) {
#pragma unroll
        for (int it = 0; it < 2; it++) {
            int linear = tid + it * 256;
            float4 v = make_float4(0.f, 0.f, 0.f, 0.f);
            int row = linear >> 2, c4 = (linear & 3) << 2;
            int gr = m0 + row, gc = k0 + c4;
            if (gr < M && gc + 3 < K)
                v = *reinterpret_cast<const float4*>(A + (size_t)gr * lda + gc);
            aR[it*4+0] = v.x; aR[it*4+1] = v.y; aR[it*4+2] = v.z; aR[it*4+3] = v.w;

            int kr = linear >> 5, n4 = (linear & 31) << 2;
            int gk2 = k0 + kr;
            float4 w = make_float4(0.f, 0.f, 0.f, 0.f);
            if (gk2 < K)
                w = *reinterpret_cast<const float4*>(B + (size_t)gk2 * 256 + n0 + n4);
            bR[it*4+0] = w.x; bR[it*4+1] = w.y; bR[it*4+2] = w.z; bR[it*4+3] = w.w;
        }
    };

    auto storeTiles = [&](int buf) {
        float* ah = sAh + buf * A_BUF; float* al = sAl + buf * A_BUF;
        float* bh = sBh + buf * B_BUF; float* bl = sBl + buf * B_BUF;
#pragma unroll
        for (int it = 0; it < 2; it++) {
            int linear = tid + it * 256;
#pragma unroll
            for (int j = 0; j < 4; j++) {
                float h, l;
                split2(aR[it*4+j], h, l);
                int row = linear >> 2, c4 = (linear & 3) << 2;
                int idx = row*ASTR + c4 + j;
                ah[idx] = h; al[idx] = l;

                split2(bR[it*4+j], h, l);
                int kr = linear >> 5, n4 = (linear & 31) << 2;
                int bidx = kr * BSTR + n4 + j;
                bh[bidx] = h; bl[bidx] = l;
            }
        }
    };

    auto computeTile = [&](int buf) {
        const float* Ah = sAh + buf * A_BUF; const float* Al = sAl + buf * A_BUF;
        const float* Bh = sBh + buf * B_BUF; const float* Bl = sBl + buf * B_BUF;
#pragma unroll
        for (int ks = 0; ks < 2; ks++) {
            int kb = ks * 8;
            uint32_t bh[4][2], bl[4][2];
#pragma unroll
            for (int ni = 0; ni < 4; ni++) {
                int cc = wn * 32 + ni * 8 + gid;
                bh[ni][0] = __float_as_uint(Bh[(kb+tig)  *BSTR + cc]);
                bh[ni][1] = __float_as_uint(Bh[(kb+tig+4)*BSTR + cc]);
                bl[ni][0] = __float_as_uint(Bl[(kb+tig)  *BSTR + cc]);
                bl[ni][1] = __float_as_uint(Bl[(kb+tig+4)*BSTR + cc]);
            }
#pragma unroll
            for (int mi = 0; mi < 4; mi++) {
                int r0 = wm * 64 + mi * 16 + gid;
                uint32_t ah[4], al[4];
#pragma unroll
                for (int q = 0; q < 4; q++) {
                    int rr = r0 + ((q & 1) ? 8 : 0);
                    int kk = kb + tig + ((q & 2) ? 4 : 0);
                    ah[q] = __float_as_uint(Ah[rr*ASTR + kk]);
                    al[q] = __float_as_uint(Al[rr*ASTR + kk]);
                }
#pragma unroll
                for (int ni = 0; ni < 4; ni++) {
                    float* a4 = &acc[(mi*4 + ni)*4];
                    mma8v(a4, al, bh[ni]);
                    mma8v(a4, ah, bl[ni]);
                    mma8v(a4, ah, bh[ni]);
                }
            }
        }
    };

    loadTiles(0);
    storeTiles(0);
    __syncthreads();
    for (int kt = 0; kt < KT; kt++) {
        if (kt + 1 < KT) loadTiles((kt + 1) * TBK);
        computeTile(kt & 1);
        // FOLD=1: fold fresh chunk into master after EVERY k-tile (precision-critical)
#pragma unroll
        for (int i = 0; i < 64; i++) { mst[i] = __fadd_rn(mst[i], acc[i]); acc[i] = 0.f; }
        if (kt + 1 < KT) storeTiles((kt + 1) & 1);
        __syncthreads();
    }

#pragma unroll
    for (int mi = 0; mi < 4; mi++) {
#pragma unroll
        for (int ni = 0; ni < 4; ni++) {
            int rB = m0 + wm * 64 + mi * 16 + gid;
            int cB = n0 + wn * 32 + ni * 8 + tig * 2;
#pragma unroll
            for (int rr = 0; rr < 2; rr++) {
                int r = rB + rr * 8;
                if (r < M) {
#pragma unroll
                    for (int c2 = 0; c2 < 2; c2++) {
                        int c = cB + c2;
                        float v = mst[(mi*4 + ni)*4 + rr * 2 + c2];
                        size_t idx = (size_t)r * 256 + c;
                        if (MODE == 1) {
                            C[idx] = 1.f / (1.f + expf(-v));
                        } else if (MODE == 2) {
                            float z = 1.f / (1.f + expf(-(v + bias[c])));
                            C[idx] = (1.f - z) * aux1[idx] + z * aux2[idx];
                        } else {
                            float t = tanhf(v);
                            float z = aux1[idx];
                            C[idx] = (1.f - z) * aux2[idx] + z * t;
                        }
                    }
                }
            }
        }
    }
}

// ---------------- elementwise kernels ----------------
__global__ void k_build_cat4(const float* __restrict__ fw, const float* __restrict__ bw,
                             float* __restrict__ cat, int total) {
    int i = blockIdx.x * blockDim.x + threadIdx.x;
    if (i >= total) return;
    int row = i >> 8, h = i & 255;
    float f = fw[i], b = bw[i];
    float* c = cat + ((size_t)row << 10) + h;
    c[0] = f; c[256] = b; c[512] = f * b; c[768] = f - b;
}

__global__ void k_build_hx(const float* __restrict__ nf, const float* __restrict__ agg,
                           float* __restrict__ hx, int total) {
    int i = blockIdx.x * blockDim.x + threadIdx.x;
    if (i >= total) return;
    int row = i >> 8, h = i & 255;
    float* p = hx + ((size_t)row << 9) + h;
    p[0] = nf[i]; p[256] = agg[i];
}

__global__ void k_build_cat2(const float* __restrict__ rg, const float* __restrict__ nf,
                             const float* __restrict__ agg, float* __restrict__ c2, int total) {
    int i = blockIdx.x * blockDim.x + threadIdx.x;
    if (i >= total) return;
    int row = i >> 8, h = i & 255;
    float* p = c2 + ((size_t)row << 9) + h;
    p[0] = rg[i] * nf[i]; p[256] = agg[i];
}

__global__ void k_transpose(const float* __restrict__ src, float* __restrict__ dst, int R, int C) {
    __shared__ float t[32][33];
    int bx = blockIdx.x * 32, by = blockIdx.y * 32;
    int x = threadIdx.x, y = threadIdx.y;
#pragma unroll
    for (int j = 0; j < 32; j += 8) {
        int r = by + y + j, c = bx + x;
        if (r < R && c < C) t[y + j][x] = src[(size_t)r * C + c];
    }
    __syncthreads();
#pragma unroll
    for (int j = 0; j < 32; j += 8) {
        int r = bx + y + j, c = by + x;
        if (r < C && c < R) dst[(size_t)r * R + c] = t[x][y + j];
    }
}

// ---------------- host side ----------------
static void run_frag(const float* pA, const float* pB, float* C, int M, int MT, int KT)
{
    cudaFuncSetAttribute(gemm_frag, cudaFuncAttributeMaxDynamicSharedMemorySize, FRAG_SMEM);
    dim3 grid(2, MT, BB);
    gemm_frag<<<grid, 256, FRAG_SMEM>>>(pA, pB, C, M, MT, KT);
}

template<int MODE>
static void run_small(const float* A, const float* B, float* C, int M, int K,
                      const float* bias, const float* a1, const float* a2)
{
    cudaFuncSetAttribute(gemm_k<MODE>, cudaFuncAttributeMaxDynamicSharedMemorySize, SMEM_BYTES);
    dim3 grid(2, (M + TBM - 1) / TBM, 1);
    gemm_k<MODE><<<grid, 256, SMEM_BYTES>>>(A, B, C, M, K, bias, a1, a2);
}

extern "C" void kernel_launch(void* const* d_in, const int* in_sizes, int n_in,
                              void* d_out, int out_size)
{
    const float* node_feature = (const float*)d_in[0];
    const float* node2edge    = (const float*)d_in[1];
    const float* edge2node    = (const float*)d_in[2];
    const float* Wz = (const float*)d_in[3];
    const float* Wr = (const float*)d_in[4];
    const float* Wt = (const float*)d_in[5];
    const float* Wf = (const float*)d_in[6];
    const float* bf = (const float*)d_in[7];
    float* out = (float*)d_out;

    float *pA1, *pA2, *pA3, *pA4, *pBnf, *pBt1, *pBt2;
    float *tmp1, *tmp2, *bwP, *fwP, *agg, *zg, *rg, *nf1, *cat4, *hx, *cat2;
    float *WfT, *WzT, *WrT, *WtT;
    cudaGetSymbolAddress((void**)&pA1, g_pA1);
    cudaGetSymbolAddress((void**)&pA2, g_pA2);
    cudaGetSymbolAddress((void**)&pA3, g_pA3);
    cudaGetSymbolAddress((void**)&pA4, g_pA4);
    cudaGetSymbolAddress((void**)&pBnf, g_pBnf);
    cudaGetSymbolAddress((void**)&pBt1, g_pBt1);
    cudaGetSymbolAddress((void**)&pBt2, g_pBt2);
    cudaGetSymbolAddress((void**)&tmp1, g_tmp1);
    cudaGetSymbolAddress((void**)&tmp2, g_tmp2);
    cudaGetSymbolAddress((void**)&bwP,  g_bw);
    cudaGetSymbolAddress((void**)&fwP,  g_fw);
    cudaGetSymbolAddress((void**)&agg,  g_agg);
    cudaGetSymbolAddress((void**)&zg,   g_zg);
    cudaGetSymbolAddress((void**)&rg,   g_rg);
    cudaGetSymbolAddress((void**)&nf1,  g_nf1);
    cudaGetSymbolAddress((void**)&cat4, g_cat4);
    cudaGetSymbolAddress((void**)&hx,   g_hx);
    cudaGetSymbolAddress((void**)&cat2, g_cat2);
    cudaGetSymbolAddress((void**)&WfT,  g_WfT);
    cudaGetSymbolAddress((void**)&WzT,  g_WzT);
    cudaGetSymbolAddress((void**)&WrT,  g_WrT);
    cudaGetSymbolAddress((void**)&WtT,  g_WtT);

    // weights transpose
    k_transpose<<<dim3(32, 8), dim3(32, 8)>>>(Wf, WfT, 256, 1024);
    k_transpose<<<dim3(16, 8), dim3(32, 8)>>>(Wz, WzT, 256, 512);
    k_transpose<<<dim3(16, 8), dim3(32, 8)>>>(Wr, WrT, 256, 512);
    k_transpose<<<dim3(16, 8), dim3(32, 8)>>>(Wt, WtT, 256, 512);

    const long long sPQ = (long long)EE * NN;
    const int TOT = BB * NN * HH;
    const int MR = BB * NN;

    // pack adjacency fragment images (reused both hops)
    k_packA<0><<<dim3(KT12, MT12, BB), 256>>>(node2edge, pA1, EE, NN, NN, sPQ, MT12, KT12);
    k_packA<1><<<dim3(KT12, MT12, BB), 256>>>(edge2node, pA2, EE, NN, EE, sPQ, MT12, KT12);
    k_packA<0><<<dim3(KT34, MT34, BB), 256>>>(edge2node, pA3, NN, EE, EE, sPQ, MT34, KT34);
    k_packA<1><<<dim3(KT34, MT34, BB), 256>>>(node2edge, pA4, NN, EE, NN, sPQ, MT34, KT34);

    const float* nfIn = node_feature;
    for (int hop = 0; hop < 2; hop++) {
        float* nfOut = (hop == 1) ? out : nf1;

        // pack nf as B image
        k_packB<<<dim3(KT12, 2, BB), 256>>>(nfIn, pBnf, NN, KT12);

        // tmp1 = node2edge @ nf ; tmp2 = edge2node^T @ nf
        run_frag(pA1, pBnf, tmp1, EE, MT12, KT12);
        run_frag(pA2, pBnf, tmp2, EE, MT12, KT12);

        // pack tmp1/tmp2 as B images
        k_packB<<<dim3(KT34, 2, BB), 256>>>(tmp1, pBt1, EE, KT34);
        k_packB<<<dim3(KT34, 2, BB), 256>>>(tmp2, pBt2, EE, KT34);

        // bw = edge2node @ tmp1 ; fw = node2edge^T @ tmp2
        run_frag(pA3, pBt1, bwP, NN, MT34, KT34);
        run_frag(pA4, pBt2, fwP, NN, MT34, KT34);

        // gated fusion
        k_build_cat4<<<TOT / 256, 256>>>(fwP, bwP, cat4, TOT);
        run_small<2>(cat4, WfT, agg, MR, 4 * HH, bf, fwP, bwP);

        // GRU step
        k_build_hx<<<TOT / 256, 256>>>(nfIn, agg, hx, TOT);
        run_small<1>(hx, WzT, zg, MR, 2 * HH, nullptr, nullptr, nullptr);
        run_small<1>(hx, WrT, rg, MR, 2 * HH, nullptr, nullptr, nullptr);
        k_build_cat2<<<TOT / 256, 256>>>(rg, nfIn, agg, cat2, TOT);
        run_small<3>(cat2, WtT, nfOut, MR, 2 * HH, nullptr, zg, nfIn);

        nfIn = nfOut;
    }
}

// round 10
// speedup vs baseline: 2.3134x; 1.0252x over previous
#include <cuda_runtime.h>
#include <cstdint>
#include <math.h>

// ---------------- problem constants ----------------
#define BB 8
#define NN 1000
#define EE 4000
#define HH 256

// Big-GEMM tiling: CTA tile 128x128, k-tile 16. Fragment-packed images:
// per (b, mtile, ktile): 4096 floats = [hi 2048][lo 2048] in mma-fragment order.
#define MT12 32      // GEMM1/2: M=4000 -> 32 tiles of 128
#define KT12 63      // K=1000  -> 63 tiles of 16
#define MT34 8       // GEMM3/4: M=1000 -> 8 tiles
#define KT34 250     // K=4000  -> 250 tiles

// small-GEMM tiling: M=8000 -> 63 tiles; K=1024 -> 64 kt; K=512 -> 32 kt
#define MTS 63
#define KTF 64
#define KTG 32

#define PA12_SZ (MT12*KT12*4096*BB)
#define PA34_SZ (MT34*KT34*4096*BB)
#define PB_NF_SZ (KT12*2*4096*BB)
#define PB_T_SZ  (KT34*2*4096*BB)
#define PACT_SZ  (MTS*KTF*4096)      // reused sequentially for cat4 / hx / cat2 images

// ---------------- scratch (static device globals; no allocation) ----------------
__device__ float g_pA1[PA12_SZ];   // node2edge normal   (M=E,K=N)
__device__ float g_pA2[PA12_SZ];   // edge2node transposed (M=E,K=N)
__device__ float g_pA3[PA34_SZ];   // edge2node normal   (M=N,K=E)
__device__ float g_pA4[PA34_SZ];   // node2edge transposed (M=N,K=E)
__device__ float g_pBnf[PB_NF_SZ];
__device__ float g_pBt1[PB_T_SZ];
__device__ float g_pBt2[PB_T_SZ];
__device__ float g_pAct[PACT_SZ];
__device__ float g_pWf[KTF*2*4096];
__device__ float g_pWz[KTG*2*4096];
__device__ float g_pWr[KTG*2*4096];
__device__ float g_pWt[KTG*2*4096];

__device__ float g_tmp1[BB*EE*HH];
__device__ float g_tmp2[BB*EE*HH];
__device__ float g_bw  [BB*NN*HH];
__device__ float g_fw  [BB*NN*HH];
__device__ float g_agg [BB*NN*HH];
__device__ float g_zg  [BB*NN*HH];
__device__ float g_rg  [BB*NN*HH];
__device__ float g_nf1 [BB*NN*HH];
__device__ float g_cat4[BB*NN*4*HH];
__device__ float g_hx  [BB*NN*2*HH];
__device__ float g_cat2[BB*NN*2*HH];
__device__ float g_WfT [4*HH*HH];
__device__ float g_WzT [2*HH*HH];
__device__ float g_WrT [2*HH*HH];
__device__ float g_WtT [2*HH*HH];

// ---------------- helpers ----------------
__device__ __forceinline__ uint32_t f2tf(float f) {
    uint32_t u; asm("cvt.rna.tf32.f32 %0, %1;" : "=r"(u) : "f"(f)); return u;
}

__device__ __forceinline__ void split2(float x, float& h, float& l) {
    uint32_t hu = f2tf(x);
    h = __uint_as_float(hu);
    float r1 = __fadd_rn(x, -h);
    uint32_t lu = f2tf(r1);
    l = __uint_as_float(lu);
}

__device__ __forceinline__ void mma8(float* d, const uint32_t* a, uint32_t b0, uint32_t b1) {
    asm volatile(
        "mma.sync.aligned.m16n8k8.row.col.f32.tf32.tf32.f32 "
        "{%0,%1,%2,%3},{%4,%5,%6,%7},{%8,%9},{%0,%1,%2,%3};"
        : "+f"(d[0]), "+f"(d[1]), "+f"(d[2]), "+f"(d[3])
        : "r"(a[0]), "r"(a[1]), "r"(a[2]), "r"(a[3]), "r"(b0), "r"(b1));
}

__device__ __forceinline__ void cp_async16(float4* smem_ptr, const float4* gptr) {
    uint32_t s = (uint32_t)__cvta_generic_to_shared(smem_ptr);
    asm volatile("cp.async.cg.shared.global [%0], [%1], 16;" :: "r"(s), "l"(gptr));
}
__device__ __forceinline__ void cp_commit() {
    asm volatile("cp.async.commit_group;");
}
template<int N>
__device__ __forceinline__ void cp_wait() {
    asm volatile("cp.async.wait_group %0;" :: "n"(N));
}

// fragment offset for A element (mRel in [0,128), kRel in [0,16)) within 2048-float plane
__device__ __forceinline__ int a_frag_off(int mRel, int kRel) {
    int ms = mRel >> 4;
    int ks2 = kRel >> 3;
    int lane = (mRel & 7) * 4 + (kRel & 3);
    int areg = ((kRel >> 2) & 1) * 2 + ((mRel >> 3) & 1);
    return (((ms * 2) + ks2) * 32 + lane) * 4 + areg;
}
// fragment offset for B element (kRel in [0,16), nRel in [0,128))
__device__ __forceinline__ int b_frag_off(int kRel, int nRel) {
    int ns = nRel >> 3;
    int lane = (nRel & 7) * 4 + (kRel & 3);
    int breg = ((kRel >> 3) & 1) * 2 + ((kRel >> 2) & 1);
    return (ns * 32 + lane) * 4 + breg;
}

// ---------------- pack kernels ----------------
template<int TRANSA>
__global__ void __launch_bounds__(256)
k_packA(const float* __restrict__ src, float* __restrict__ dst,
        int M, int K, int lda, long long sSrc, int MT, int KT)
{
    __shared__ float img[4096];
    int kt = blockIdx.x, mt = blockIdx.y, b = blockIdx.z;
    const float* S = src + (long long)b * sSrc;
    int m0 = mt * 128, k0 = kt * 16;
    int tid = threadIdx.x;
#pragma unroll
    for (int it = 0; it < 2; it++) {
        int linear = tid + it * 256;
        float4 v = make_float4(0.f, 0.f, 0.f, 0.f);
        int mR[4], kR[4];
        if (TRANSA == 0) {
            int row = linear >> 2, c4 = (linear & 3) << 2;
            int gm = m0 + row, gk = k0 + c4;
            if (gm < M) {
                if (gk + 3 < K) v = *reinterpret_cast<const float4*>(S + (size_t)gm * lda + gk);
                else {
                    float* p = &v.x;
#pragma unroll
                    for (int j = 0; j < 4; j++) if (gk + j < K) p[j] = S[(size_t)gm * lda + gk + j];
                }
            }
#pragma unroll
            for (int j = 0; j < 4; j++) { mR[j] = row; kR[j] = c4 + j; }
        } else {
            int kk = linear >> 5, m4 = (linear & 31) << 2;
            int gk = k0 + kk, gm = m0 + m4;
            if (gk < K) {
                if (gm + 3 < M) v = *reinterpret_cast<const float4*>(S + (size_t)gk * lda + gm);
                else {
                    float* p = &v.x;
#pragma unroll
                    for (int j = 0; j < 4; j++) if (gm + j < M) p[j] = S[(size_t)gk * lda + gm + j];
                }
            }
#pragma unroll
            for (int j = 0; j < 4; j++) { mR[j] = m4 + j; kR[j] = kk; }
        }
        const float* pv = &v.x;
#pragma unroll
        for (int j = 0; j < 4; j++) {
            float h, l;
            split2(pv[j], h, l);
            int off = a_frag_off(mR[j], kR[j]);
            img[off] = h; img[2048 + off] = l;
        }
    }
    __syncthreads();
    float4* D = reinterpret_cast<float4*>(dst + (((long long)b * MT + mt) * KT + kt) * 4096);
    const float4* I = reinterpret_cast<const float4*>(img);
#pragma unroll
    for (int i = 0; i < 4; i++) D[tid + i * 256] = I[tid + i * 256];
}

__global__ void __launch_bounds__(256)
k_packB(const float* __restrict__ src, float* __restrict__ dst, int K, int KT)
{
    __shared__ float img[4096];
    int kt = blockIdx.x, nt = blockIdx.y, b = blockIdx.z;
    const float* S = src + (long long)b * K * 256;
    int k0 = kt * 16, n0 = nt * 128;
    int tid = threadIdx.x;
#pragma unroll
    for (int it = 0; it < 2; it++) {
        int linear = tid + it * 256;
        int kr = linear >> 5, n4 = (linear & 31) << 2;
        int gk = k0 + kr;
        float4 v = make_float4(0.f, 0.f, 0.f, 0.f);
        if (gk < K) v = *reinterpret_cast<const float4*>(S + (size_t)gk * 256 + n0 + n4);
        const float* pv = &v.x;
#pragma unroll
        for (int j = 0; j < 4; j++) {
            float h, l;
            split2(pv[j], h, l);
            int off = b_frag_off(kr, n4 + j);
            img[off] = h; img[2048 + off] = l;
        }
    }
    __syncthreads();
    float4* D = reinterpret_cast<float4*>(dst + (((long long)b * KT + kt) * 2 + nt) * 4096);
    const float4* I = reinterpret_cast<const float4*>(img);
#pragma unroll
    for (int i = 0; i < 4; i++) D[tid + i * 256] = I[tid + i * 256];
}

// ---------------- fragment GEMM with 4-stage cp.async pipeline ----------------
// MODE: 0=store, 1=sigmoid, 2=gated fusion (bias, aux1=fw, aux2=bw), 3=GRU out (aux1=z, aux2=h_old)
// FOLD: fold fresh accumulator into master every FOLD k-tiles (FOLD=1 is precision-critical
// for the large-magnitude fusion/GRU GEMMs — see R6 regression)
#define STAGES 4
#define FRAG_SMEM (STAGES*8192*4)   // 131072 bytes

template<int MODE, int FOLD>
__global__ void __launch_bounds__(256)
gemm_frag(const float* __restrict__ pA, const float* __restrict__ pB, float* __restrict__ C,
          int M, int MT, int KT,
          const float* __restrict__ bias,
          const float* __restrict__ aux1, const float* __restrict__ aux2)
{
    extern __shared__ float sm[];   // STAGES x (A 4096 + B 4096) floats
    const int tid = threadIdx.x;
    const int nt = blockIdx.x, mt = blockIdx.y, b = blockIdx.z;
    const float4* Abase = reinterpret_cast<const float4*>(pA) + ((long long)b * MT + mt) * KT * 1024;
    const float4* Bbase = reinterpret_cast<const float4*>(pB) + (long long)b * KT * 2048;

    const int lane = tid & 31, warp = tid >> 5;
    const int wm = warp >> 2, wn = warp & 3;
    const int gid = lane >> 2, tig = lane & 3;

    float acc[64], mst[64];
#pragma unroll
    for (int i = 0; i < 64; i++) { acc[i] = 0.f; mst[i] = 0.f; }

    auto issue = [&](int kt) {
        float4* s = reinterpret_cast<float4*>(sm + (kt % STAGES) * 8192);
        const float4* A = Abase + (size_t)kt * 1024;
        const float4* Bt = Bbase + ((size_t)kt * 2 + nt) * 1024;
#pragma unroll
        for (int i = 0; i < 4; i++) cp_async16(s + tid + i * 256, A + tid + i * 256);
#pragma unroll
        for (int i = 0; i < 4; i++) cp_async16(s + 1024 + tid + i * 256, Bt + tid + i * 256);
    };

    auto compute = [&](int stage) {
        const float* sA = sm + stage * 8192;
        const float* sB = sm + stage * 8192 + 4096;
        float4 bh[4], bl[4];
#pragma unroll
        for (int ni = 0; ni < 4; ni++) {
            int ns = wn * 4 + ni;
            bh[ni] = *reinterpret_cast<const float4*>(sB + (ns * 32 + lane) * 4);
            bl[ni] = *reinterpret_cast<const float4*>(sB + 2048 + (ns * 32 + lane) * 4);
        }
#pragma unroll
        for (int ks = 0; ks < 2; ks++) {
#pragma unroll
            for (int mi = 0; mi < 4; mi++) {
                int ms = wm * 4 + mi;
                float4 a4h = *reinterpret_cast<const float4*>(sA + ((ms * 2 + ks) * 32 + lane) * 4);
                float4 a4l = *reinterpret_cast<const float4*>(sA + 2048 + ((ms * 2 + ks) * 32 + lane) * 4);
                uint32_t ah[4] = {__float_as_uint(a4h.x), __float_as_uint(a4h.y),
                                  __float_as_uint(a4h.z), __float_as_uint(a4h.w)};
                uint32_t al[4] = {__float_as_uint(a4l.x), __float_as_uint(a4l.y),
                                  __float_as_uint(a4l.z), __float_as_uint(a4l.w)};
#pragma unroll
                for (int ni = 0; ni < 4; ni++) {
                    float* a4 = &acc[(mi * 4 + ni) * 4];
                    uint32_t bhk0 = (ks == 0) ? __float_as_uint(bh[ni].x) : __float_as_uint(bh[ni].z);
                    uint32_t bhk1 = (ks == 0) ? __float_as_uint(bh[ni].y) : __float_as_uint(bh[ni].w);
                    uint32_t blk0 = (ks == 0) ? __float_as_uint(bl[ni].x) : __float_as_uint(bl[ni].z);
                    uint32_t blk1 = (ks == 0) ? __float_as_uint(bl[ni].y) : __float_as_uint(bl[ni].w);
                    mma8(a4, al, bhk0, bhk1);
                    mma8(a4, ah, blk0, blk1);
                    mma8(a4, ah, bhk0, bhk1);
                }
            }
        }
    };

    // prologue: fill STAGES-1 stages
    const int PRE = STAGES - 1;
#pragma unroll
    for (int s = 0; s < PRE; s++) {
        if (s < KT) issue(s);
        cp_commit();
    }

    for (int kt = 0; kt < KT; kt++) {
        cp_wait<STAGES - 2>();
        __syncthreads();
        compute(kt % STAGES);
        if (((kt + 1) % FOLD) == 0 || kt == KT - 1) {
#pragma unroll
            for (int i = 0; i < 64; i++) { mst[i] = __fadd_rn(mst[i], acc[i]); acc[i] = 0.f; }
        }
        if (kt + PRE < KT) issue(kt + PRE);
        cp_commit();
    }

    float* Cb = C + (long long)b * M * 256;
#pragma unroll
    for (int mi = 0; mi < 4; mi++) {
#pragma unroll
        for (int ni = 0; ni < 4; ni++) {
            int rB = mt * 128 + wm * 64 + mi * 16 + gid;
            int cB = nt * 128 + wn * 32 + ni * 8 + tig * 2;
#pragma unroll
            for (int rr = 0; rr < 2; rr++) {
                int r = rB + rr * 8;
                if (r < M) {
#pragma unroll
                    for (int c2 = 0; c2 < 2; c2++) {
                        int c = cB + c2;
                        float v = mst[(mi * 4 + ni) * 4 + rr * 2 + c2];
                        size_t idx = (size_t)r * 256 + c;
                        if (MODE == 0) {
                            Cb[idx] = v;
                        } else if (MODE == 1) {
                            Cb[idx] = 1.f / (1.f + expf(-v));
                        } else if (MODE == 2) {
                            float z = 1.f / (1.f + expf(-(v + bias[c])));
                            Cb[idx] = (1.f - z) * aux1[idx] + z * aux2[idx];
                        } else {
                            float t = tanhf(v);
                            float z = aux1[idx];
                            Cb[idx] = (1.f - z) * aux2[idx] + z * t;
                        }
                    }
                }
            }
        }
    }
}

// ---------------- elementwise kernels ----------------
__global__ void k_build_cat4(const float* __restrict__ fw, const float* __restrict__ bw,
                             float* __restrict__ cat, int total) {
    int i = blockIdx.x * blockDim.x + threadIdx.x;
    if (i >= total) return;
    int row = i >> 8, h = i & 255;
    float f = fw[i], b = bw[i];
    float* c = cat + ((size_t)row << 10) + h;
    c[0] = f; c[256] = b; c[512] = f * b; c[768] = f - b;
}

__global__ void k_build_hx(const float* __restrict__ nf, const float* __restrict__ agg,
                           float* __restrict__ hx, int total) {
    int i = blockIdx.x * blockDim.x + threadIdx.x;
    if (i >= total) return;
    int row = i >> 8, h = i & 255;
    float* p = hx + ((size_t)row << 9) + h;
    p[0] = nf[i]; p[256] = agg[i];
}

__global__ void k_build_cat2(const float* __restrict__ rg, const float* __restrict__ nf,
                             const float* __restrict__ agg, float* __restrict__ c2, int total) {
    int i = blockIdx.x * blockDim.x + threadIdx.x;
    if (i >= total) return;
    int row = i >> 8, h = i & 255;
    float* p = c2 + ((size_t)row << 9) + h;
    p[0] = rg[i] * nf[i]; p[256] = agg[i];
}

__global__ void k_transpose(const float* __restrict__ src, float* __restrict__ dst, int R, int C) {
    __shared__ float t[32][33];
    int bx = blockIdx.x * 32, by = blockIdx.y * 32;
    int x = threadIdx.x, y = threadIdx.y;
#pragma unroll
    for (int j = 0; j < 32; j += 8) {
        int r = by + y + j, c = bx + x;
        if (r < R && c < C) t[y + j][x] = src[(size_t)r * C + c];
    }
    __syncthreads();
#pragma unroll
    for (int j = 0; j < 32; j += 8) {
        int r = bx + y + j, c = by + x;
        if (r < C && c < R) dst[(size_t)r * R + c] = t[x][y + j];
    }
}

// ---------------- host side ----------------
template<int MODE, int FOLD>
static void run_frag(const float* pA, const float* pB, float* C, int M, int MT, int KT, int batch,
                     const float* bias, const float* a1, const float* a2)
{
    cudaFuncSetAttribute(gemm_frag<MODE, FOLD>, cudaFuncAttributeMaxDynamicSharedMemorySize, FRAG_SMEM);
    dim3 grid(2, MT, batch);
    gemm_frag<MODE, FOLD><<<grid, 256, FRAG_SMEM>>>(pA, pB, C, M, MT, KT, bias, a1, a2);
}

extern "C" void kernel_launch(void* const* d_in, const int* in_sizes, int n_in,
                              void* d_out, int out_size)
{
    const float* node_feature = (const float*)d_in[0];
    const float* node2edge    = (const float*)d_in[1];
    const float* edge2node    = (const float*)d_in[2];
    const float* Wz = (const float*)d_in[3];
    const float* Wr = (const float*)d_in[4];
    const float* Wt = (const float*)d_in[5];
    const float* Wf = (const float*)d_in[6];
    const float* bf = (const float*)d_in[7];
    float* out = (float*)d_out;

    float *pA1, *pA2, *pA3, *pA4, *pBnf, *pBt1, *pBt2, *pAct, *pWf, *pWz, *pWr, *pWt;
    float *tmp1, *tmp2, *bwP, *fwP, *agg, *zg, *rg, *nf1, *cat4, *hx, *cat2;
    float *WfT, *WzT, *WrT, *WtT;
    cudaGetSymbolAddress((void**)&pA1, g_pA1);
    cudaGetSymbolAddress((void**)&pA2, g_pA2);
    cudaGetSymbolAddress((void**)&pA3, g_pA3);
    cudaGetSymbolAddress((void**)&pA4, g_pA4);
    cudaGetSymbolAddress((void**)&pBnf, g_pBnf);
    cudaGetSymbolAddress((void**)&pBt1, g_pBt1);
    cudaGetSymbolAddress((void**)&pBt2, g_pBt2);
    cudaGetSymbolAddress((void**)&pAct, g_pAct);
    cudaGetSymbolAddress((void**)&pWf, g_pWf);
    cudaGetSymbolAddress((void**)&pWz, g_pWz);
    cudaGetSymbolAddress((void**)&pWr, g_pWr);
    cudaGetSymbolAddress((void**)&pWt, g_pWt);
    cudaGetSymbolAddress((void**)&tmp1, g_tmp1);
    cudaGetSymbolAddress((void**)&tmp2, g_tmp2);
    cudaGetSymbolAddress((void**)&bwP,  g_bw);
    cudaGetSymbolAddress((void**)&fwP,  g_fw);
    cudaGetSymbolAddress((void**)&agg,  g_agg);
    cudaGetSymbolAddress((void**)&zg,   g_zg);
    cudaGetSymbolAddress((void**)&rg,   g_rg);
    cudaGetSymbolAddress((void**)&nf1,  g_nf1);
    cudaGetSymbolAddress((void**)&cat4, g_cat4);
    cudaGetSymbolAddress((void**)&hx,   g_hx);
    cudaGetSymbolAddress((void**)&cat2, g_cat2);
    cudaGetSymbolAddress((void**)&WfT,  g_WfT);
    cudaGetSymbolAddress((void**)&WzT,  g_WzT);
    cudaGetSymbolAddress((void**)&WrT,  g_WrT);
    cudaGetSymbolAddress((void**)&WtT,  g_WtT);

    // weights transpose + weight B-images (once per call)
    k_transpose<<<dim3(32, 8), dim3(32, 8)>>>(Wf, WfT, 256, 1024);
    k_transpose<<<dim3(16, 8), dim3(32, 8)>>>(Wz, WzT, 256, 512);
    k_transpose<<<dim3(16, 8), dim3(32, 8)>>>(Wr, WrT, 256, 512);
    k_transpose<<<dim3(16, 8), dim3(32, 8)>>>(Wt, WtT, 256, 512);
    k_packB<<<dim3(KTF, 2, 1), 256>>>(WfT, pWf, 4 * HH, KTF);
    k_packB<<<dim3(KTG, 2, 1), 256>>>(WzT, pWz, 2 * HH, KTG);
    k_packB<<<dim3(KTG, 2, 1), 256>>>(WrT, pWr, 2 * HH, KTG);
    k_packB<<<dim3(KTG, 2, 1), 256>>>(WtT, pWt, 2 * HH, KTG);

    const long long sPQ = (long long)EE * NN;
    const int TOT = BB * NN * HH;
    const int MR = BB * NN;   // 8000

    // pack adjacency fragment images (reused both hops)
    k_packA<0><<<dim3(KT12, MT12, BB), 256>>>(node2edge, pA1, EE, NN, NN, sPQ, MT12, KT12);
    k_packA<1><<<dim3(KT12, MT12, BB), 256>>>(edge2node, pA2, EE, NN, EE, sPQ, MT12, KT12);
    k_packA<0><<<dim3(KT34, MT34, BB), 256>>>(edge2node, pA3, NN, EE, EE, sPQ, MT34, KT34);
    k_packA<1><<<dim3(KT34, MT34, BB), 256>>>(node2edge, pA4, NN, EE, NN, sPQ, MT34, KT34);

    const float* nfIn = node_feature;
    for (int hop = 0; hop < 2; hop++) {
        float* nfOut = (hop == 1) ? out : nf1;

        // pack nf as B image
        k_packB<<<dim3(KT12, 2, BB), 256>>>(nfIn, pBnf, NN, KT12);

        // tmp1 = node2edge @ nf ; tmp2 = edge2node^T @ nf
        run_frag<0, 4>(pA1, pBnf, tmp1, EE, MT12, KT12, BB, nullptr, nullptr, nullptr);
        run_frag<0, 4>(pA2, pBnf, tmp2, EE, MT12, KT12, BB, nullptr, nullptr, nullptr);

        // pack tmp1/tmp2 as B images
        k_packB<<<dim3(KT34, 2, BB), 256>>>(tmp1, pBt1, EE, KT34);
        k_packB<<<dim3(KT34, 2, BB), 256>>>(tmp2, pBt2, EE, KT34);

        // bw = edge2node @ tmp1 ; fw = node2edge^T @ tmp2
        run_frag<0, 4>(pA3, pBt1, bwP, NN, MT34, KT34, BB, nullptr, nullptr, nullptr);
        run_frag<0, 4>(pA4, pBt2, fwP, NN, MT34, KT34, BB, nullptr, nullptr, nullptr);

        // gated fusion: agg = (1-z)*fw + z*bw, z = sigmoid(cat4 @ WfT + bf)
        k_build_cat4<<<TOT / 256, 256>>>(fwP, bwP, cat4, TOT);
        k_packA<0><<<dim3(KTF, MTS, 1), 256>>>(cat4, pAct, MR, 4 * HH, 4 * HH, 0, MTS, KTF);
        run_frag<2, 1>(pAct, pWf, agg, MR, MTS, KTF, 1, bf, fwP, bwP);

        // GRU step
        k_build_hx<<<TOT / 256, 256>>>(nfIn, agg, hx, TOT);
        k_packA<0><<<dim3(KTG, MTS, 1), 256>>>(hx, pAct, MR, 2 * HH, 2 * HH, 0, MTS, KTG);
        run_frag<1, 1>(pAct, pWz, zg, MR, MTS, KTG, 1, nullptr, nullptr, nullptr);
        run_frag<1, 1>(pAct, pWr, rg, MR, MTS, KTG, 1, nullptr, nullptr, nullptr);
        k_build_cat2<<<TOT / 256, 256>>>(rg, nfIn, agg, cat2, TOT);
        k_packA<0><<<dim3(KTG, MTS, 1), 256>>>(cat2, pAct, MR, 2 * HH, 2 * HH, 0, MTS, KTG);
        run_frag<3, 1>(pAct, pWt, nfOut, MR, MTS, KTG, 1, nullptr, zg, nfIn);

        nfIn = nfOut;
    }
}

// round 11
// speedup vs baseline: 2.3614x; 1.0208x over previous
#include <cuda_runtime.h>
#include <cstdint>
#include <math.h>

// ---------------- problem constants ----------------
#define BB 8
#define NN 1000
#define EE 4000
#define HH 256

// Big-GEMM tiling: CTA tile 128x128, k-tile 16. Fragment-packed images:
// per (b, mtile, ktile): 4096 floats = [hi 2048][lo 2048] in mma-fragment order.
#define MT12 32      // GEMM1/2: M=4000 -> 32 tiles of 128
#define KT12 63      // K=1000  -> 63 tiles of 16
#define MT34 8       // GEMM3/4: M=1000 -> 8 tiles
#define KT34 250     // K=4000  -> 250 tiles

// small-GEMM tiling: M=8000 -> 63 tiles; K=1024 -> 64 kt; K=512 -> 32 kt
#define MTS 63
#define KTF 64
#define KTG 32

#define PA12_SZ (MT12*KT12*4096*BB)
#define PA34_SZ (MT34*KT34*4096*BB)
#define PB_NF_SZ (KT12*2*4096*BB)
#define PB_T_SZ  (KT34*2*4096*BB)
#define PACT_SZ  (MTS*KTF*4096)      // reused sequentially for cat4 / hx / cat2 images

// ---------------- scratch (static device globals; no allocation) ----------------
__device__ float g_pA1[PA12_SZ];   // node2edge normal   (M=E,K=N)
__device__ float g_pA2[PA12_SZ];   // edge2node transposed (M=E,K=N)
__device__ float g_pA3[PA34_SZ];   // edge2node normal   (M=N,K=E)
__device__ float g_pA4[PA34_SZ];   // node2edge transposed (M=N,K=E)
__device__ float g_pBnf[PB_NF_SZ];
__device__ float g_pBt1[PB_T_SZ];
__device__ float g_pBt2[PB_T_SZ];
__device__ float g_pAct[PACT_SZ];
__device__ float g_pWf[KTF*2*4096];
__device__ float g_pWz[KTG*2*4096];
__device__ float g_pWr[KTG*2*4096];
__device__ float g_pWt[KTG*2*4096];

__device__ float g_tmp1[BB*EE*HH];
__device__ float g_tmp2[BB*EE*HH];
__device__ float g_bw  [BB*NN*HH];
__device__ float g_fw  [BB*NN*HH];
__device__ float g_agg [BB*NN*HH];
__device__ float g_zg  [BB*NN*HH];
__device__ float g_rg  [BB*NN*HH];
__device__ float g_nf1 [BB*NN*HH];
__device__ float g_WfT [4*HH*HH];
__device__ float g_WzT [2*HH*HH];
__device__ float g_WrT [2*HH*HH];
__device__ float g_WtT [2*HH*HH];

// ---------------- helpers ----------------
__device__ __forceinline__ uint32_t f2tf(float f) {
    uint32_t u; asm("cvt.rna.tf32.f32 %0, %1;" : "=r"(u) : "f"(f)); return u;
}

__device__ __forceinline__ void split2(float x, float& h, float& l) {
    uint32_t hu = f2tf(x);
    h = __uint_as_float(hu);
    float r1 = __fadd_rn(x, -h);
    uint32_t lu = f2tf(r1);
    l = __uint_as_float(lu);
}

__device__ __forceinline__ void mma8(float* d, const uint32_t* a, uint32_t b0, uint32_t b1) {
    asm volatile(
        "mma.sync.aligned.m16n8k8.row.col.f32.tf32.tf32.f32 "
        "{%0,%1,%2,%3},{%4,%5,%6,%7},{%8,%9},{%0,%1,%2,%3};"
        : "+f"(d[0]), "+f"(d[1]), "+f"(d[2]), "+f"(d[3])
        : "r"(a[0]), "r"(a[1]), "r"(a[2]), "r"(a[3]), "r"(b0), "r"(b1));
}

__device__ __forceinline__ void cp_async16(float4* smem_ptr, const float4* gptr) {
    uint32_t s = (uint32_t)__cvta_generic_to_shared(smem_ptr);
    asm volatile("cp.async.cg.shared.global [%0], [%1], 16;" :: "r"(s), "l"(gptr));
}
__device__ __forceinline__ void cp_commit() {
    asm volatile("cp.async.commit_group;");
}
template<int N>
__device__ __forceinline__ void cp_wait() {
    asm volatile("cp.async.wait_group %0;" :: "n"(N));
}

// fragment offset for A element (mRel in [0,128), kRel in [0,16)) within 2048-float plane
__device__ __forceinline__ int a_frag_off(int mRel, int kRel) {
    int ms = mRel >> 4;
    int ks2 = kRel >> 3;
    int lane = (mRel & 7) * 4 + (kRel & 3);
    int areg = ((kRel >> 2) & 1) * 2 + ((mRel >> 3) & 1);
    return (((ms * 2) + ks2) * 32 + lane) * 4 + areg;
}
// fragment offset for B element (kRel in [0,16), nRel in [0,128))
__device__ __forceinline__ int b_frag_off(int kRel, int nRel) {
    int ns = nRel >> 3;
    int lane = (nRel & 7) * 4 + (kRel & 3);
    int breg = ((kRel >> 3) & 1) * 2 + ((kRel >> 2) & 1);
    return (ns * 32 + lane) * 4 + breg;
}

// ---------------- pack kernels ----------------
template<int TRANSA>
__global__ void __launch_bounds__(256)
k_packA(const float* __restrict__ src, float* __restrict__ dst,
        int M, int K, int lda, long long sSrc, int MT, int KT)
{
    __shared__ float img[4096];
    int kt = blockIdx.x, mt = blockIdx.y, b = blockIdx.z;
    const float* S = src + (long long)b * sSrc;
    int m0 = mt * 128, k0 = kt * 16;
    int tid = threadIdx.x;
#pragma unroll
    for (int it = 0; it < 2; it++) {
        int linear = tid + it * 256;
        float4 v = make_float4(0.f, 0.f, 0.f, 0.f);
        int mR[4], kR[4];
        if (TRANSA == 0) {
            int row = linear >> 2, c4 = (linear & 3) << 2;
            int gm = m0 + row, gk = k0 + c4;
            if (gm < M) {
                if (gk + 3 < K) v = *reinterpret_cast<const float4*>(S + (size_t)gm * lda + gk);
                else {
                    float* p = &v.x;
#pragma unroll
                    for (int j = 0; j < 4; j++) if (gk + j < K) p[j] = S[(size_t)gm * lda + gk + j];
                }
            }
#pragma unroll
            for (int j = 0; j < 4; j++) { mR[j] = row; kR[j] = c4 + j; }
        } else {
            int kk = linear >> 5, m4 = (linear & 31) << 2;
            int gk = k0 + kk, gm = m0 + m4;
            if (gk < K) {
                if (gm + 3 < M) v = *reinterpret_cast<const float4*>(S + (size_t)gk * lda + gm);
                else {
                    float* p = &v.x;
#pragma unroll
                    for (int j = 0; j < 4; j++) if (gm + j < M) p[j] = S[(size_t)gk * lda + gm + j];
                }
            }
#pragma unroll
            for (int j = 0; j < 4; j++) { mR[j] = m4 + j; kR[j] = kk; }
        }
        const float* pv = &v.x;
#pragma unroll
        for (int j = 0; j < 4; j++) {
            float h, l;
            split2(pv[j], h, l);
            int off = a_frag_off(mR[j], kR[j]);
            img[off] = h; img[2048 + off] = l;
        }
    }
    __syncthreads();
    float4* D = reinterpret_cast<float4*>(dst + (((long long)b * MT + mt) * KT + kt) * 4096);
    const float4* I = reinterpret_cast<const float4*>(img);
#pragma unroll
    for (int i = 0; i < 4; i++) D[tid + i * 256] = I[tid + i * 256];
}

// Fused activation A-pack: builds cat4/hx/cat2 values on the fly (fp32, identical bits to
// the old build+pack pair) and writes the fragment image directly. M=8000 fixed.
// SRC 0: cat4 [fw,bw,fw*bw,fw-bw] K=1024 (s1=fw, s2=bw)
// SRC 1: hx   [nf,agg]            K=512  (s1=nf, s2=agg)
// SRC 2: cat2 [rg*nf,agg]         K=512  (s1=rg, s2=nf, s3=agg)
template<int SRC>
__global__ void __launch_bounds__(256)
k_packA_f(const float* __restrict__ s1, const float* __restrict__ s2, const float* __restrict__ s3,
          float* __restrict__ dst, int KT)
{
    __shared__ float img[4096];
    int kt = blockIdx.x, mt = blockIdx.y;
    int m0 = mt * 128, k0 = kt * 16;
    int tid = threadIdx.x;
#pragma unroll
    for (int it = 0; it < 2; it++) {
        int linear = tid + it * 256;
        int row = linear >> 2, c4 = (linear & 3) << 2;
        int gm = m0 + row;
#pragma unroll
        for (int j = 0; j < 4; j++) {
            int gk = k0 + c4 + j;
            float val = 0.f;
            if (gm < BB * NN) {
                if (SRC == 0) {
                    int feat = gk >> 8, hcol = gk & 255;
                    float f = s1[(size_t)gm * 256 + hcol];
                    float b = s2[(size_t)gm * 256 + hcol];
                    val = (feat == 0) ? f : (feat == 1) ? b : (feat == 2) ? f * b : f - b;
                } else if (SRC == 1) {
                    val = (gk < 256) ? s1[(size_t)gm * 256 + gk]
                                     : s2[(size_t)gm * 256 + (gk - 256)];
                } else {
                    val = (gk < 256) ? s1[(size_t)gm * 256 + gk] * s2[(size_t)gm * 256 + gk]
                                     : s3[(size_t)gm * 256 + (gk - 256)];
                }
            }
            float h, l;
            split2(val, h, l);
            int off = a_frag_off(row, c4 + j);
            img[off] = h; img[2048 + off] = l;
        }
    }
    __syncthreads();
    float4* D = reinterpret_cast<float4*>(dst + ((long long)mt * KT + kt) * 4096);
    const float4* I = reinterpret_cast<const float4*>(img);
#pragma unroll
    for (int i = 0; i < 4; i++) D[tid + i * 256] = I[tid + i * 256];
}

__global__ void __launch_bounds__(256)
k_packB(const float* __restrict__ src, float* __restrict__ dst, int K, int KT)
{
    __shared__ float img[4096];
    int kt = blockIdx.x, nt = blockIdx.y, b = blockIdx.z;
    const float* S = src + (long long)b * K * 256;
    int k0 = kt * 16, n0 = nt * 128;
    int tid = threadIdx.x;
#pragma unroll
    for (int it = 0; it < 2; it++) {
        int linear = tid + it * 256;
        int kr = linear >> 5, n4 = (linear & 31) << 2;
        int gk = k0 + kr;
        float4 v = make_float4(0.f, 0.f, 0.f, 0.f);
        if (gk < K) v = *reinterpret_cast<const float4*>(S + (size_t)gk * 256 + n0 + n4);
        const float* pv = &v.x;
#pragma unroll
        for (int j = 0; j < 4; j++) {
            float h, l;
            split2(pv[j], h, l);
            int off = b_frag_off(kr, n4 + j);
            img[off] = h; img[2048 + off] = l;
        }
    }
    __syncthreads();
    float4* D = reinterpret_cast<float4*>(dst + (((long long)b * KT + kt) * 2 + nt) * 4096);
    const float4* I = reinterpret_cast<const float4*>(img);
#pragma unroll
    for (int i = 0; i < 4; i++) D[tid + i * 256] = I[tid + i * 256];
}

// ---------------- fragment GEMM: 6-tile ring, 2-tile granules, cp.async ----------------
// MODE: 0=store, 1=sigmoid, 2=gated fusion (bias, aux1=fw, aux2=bw), 3=GRU out (aux1=z, aux2=h_old)
// FOLD: fold fresh accumulator into master every FOLD k-tiles (FOLD=1 is precision-critical
// for the large-magnitude fusion/GRU GEMMs — R6 regression)
#define STAGES_T 6
#define FRAG_SMEM (STAGES_T*8192*4)   // 196608 bytes

template<int MODE, int FOLD>
__global__ void __launch_bounds__(256)
gemm_frag(const float* __restrict__ pA, const float* __restrict__ pB, float* __restrict__ C,
          int M, int MT, int KT,
          const float* __restrict__ bias,
          const float* __restrict__ aux1, const float* __restrict__ aux2)
{
    extern __shared__ float sm[];   // STAGES_T x (A 4096 + B 4096) floats
    const int tid = threadIdx.x;
    const int nt = blockIdx.x, mt = blockIdx.y, b = blockIdx.z;
    const float4* Abase = reinterpret_cast<const float4*>(pA) + ((long long)b * MT + mt) * KT * 1024;
    const float4* Bbase = reinterpret_cast<const float4*>(pB) + (long long)b * KT * 2048;

    const int lane = tid & 31, warp = tid >> 5;
    const int wm = warp >> 2, wn = warp & 3;
    const int gid = lane >> 2, tig = lane & 3;

    float acc[64], mst[64];
#pragma unroll
    for (int i = 0; i < 64; i++) { acc[i] = 0.f; mst[i] = 0.f; }

    auto issue = [&](int kt) {
        float4* s = reinterpret_cast<float4*>(sm + (kt % STAGES_T) * 8192);
        const float4* A = Abase + (size_t)kt * 1024;
        const float4* Bt = Bbase + ((size_t)kt * 2 + nt) * 1024;
#pragma unroll
        for (int i = 0; i < 4; i++) cp_async16(s + tid + i * 256, A + tid + i * 256);
#pragma unroll
        for (int i = 0; i < 4; i++) cp_async16(s + 1024 + tid + i * 256, Bt + tid + i * 256);
    };
    auto issueG = [&](int g) {    // granule = 2 k-tiles, one commit group
        int kt0 = g * 2;
        if (kt0 < KT) issue(kt0);
        if (kt0 + 1 < KT) issue(kt0 + 1);
    };

    auto compute = [&](int stage) {
        const float* sA = sm + stage * 8192;
        const float* sB = sm + stage * 8192 + 4096;
        float4 bh[4], bl[4];
#pragma unroll
        for (int ni = 0; ni < 4; ni++) {
            int ns = wn * 4 + ni;
            bh[ni] = *reinterpret_cast<const float4*>(sB + (ns * 32 + lane) * 4);
            bl[ni] = *reinterpret_cast<const float4*>(sB + 2048 + (ns * 32 + lane) * 4);
        }
#pragma unroll
        for (int ks = 0; ks < 2; ks++) {
#pragma unroll
            for (int mi = 0; mi < 4; mi++) {
                int ms = wm * 4 + mi;
                float4 a4h = *reinterpret_cast<const float4*>(sA + ((ms * 2 + ks) * 32 + lane) * 4);
                float4 a4l = *reinterpret_cast<const float4*>(sA + 2048 + ((ms * 2 + ks) * 32 + lane) * 4);
                uint32_t ah[4] = {__float_as_uint(a4h.x), __float_as_uint(a4h.y),
                                  __float_as_uint(a4h.z), __float_as_uint(a4h.w)};
                uint32_t al[4] = {__float_as_uint(a4l.x), __float_as_uint(a4l.y),
                                  __float_as_uint(a4l.z), __float_as_uint(a4l.w)};
#pragma unroll
                for (int ni = 0; ni < 4; ni++) {
                    float* a4 = &acc[(mi * 4 + ni) * 4];
                    uint32_t bhk0 = (ks == 0) ? __float_as_uint(bh[ni].x) : __float_as_uint(bh[ni].z);
                    uint32_t bhk1 = (ks == 0) ? __float_as_uint(bh[ni].y) : __float_as_uint(bh[ni].w);
                    uint32_t blk0 = (ks == 0) ? __float_as_uint(bl[ni].x) : __float_as_uint(bl[ni].z);
                    uint32_t blk1 = (ks == 0) ? __float_as_uint(bl[ni].y) : __float_as_uint(bl[ni].w);
                    mma8(a4, al, bhk0, bhk1);
                    mma8(a4, ah, blk0, blk1);
                    mma8(a4, ah, bhk0, bhk1);
                }
            }
        }
    };

    auto fold = [&]() {
#pragma unroll
        for (int i = 0; i < 64; i++) { mst[i] = __fadd_rn(mst[i], acc[i]); acc[i] = 0.f; }
    };

    const int NG = (KT + 1) >> 1;
    // prologue: 2 granules in flight
    issueG(0); cp_commit();
    issueG(1); cp_commit();

    for (int g = 0; g < NG; g++) {
        cp_wait<1>();        // granule g landed (granule g+1 may still be pending)
        __syncthreads();
        int kt = g * 2;
        compute(kt % STAGES_T);
        if (((kt + 1) % FOLD) == 0 || kt == KT - 1) fold();
        if (kt + 1 < KT) {
            compute((kt + 1) % STAGES_T);
            if (((kt + 2) % FOLD) == 0 || kt + 1 == KT - 1) fold();
        }
        issueG(g + 2);
        cp_commit();         // uniform group accounting (possibly empty group)
    }

    float* Cb = C + (long long)b * M * 256;
#pragma unroll
    for (int mi = 0; mi < 4; mi++) {
#pragma unroll
        for (int ni = 0; ni < 4; ni++) {
            int rB = mt * 128 + wm * 64 + mi * 16 + gid;
            int cB = nt * 128 + wn * 32 + ni * 8 + tig * 2;
#pragma unroll
            for (int rr = 0; rr < 2; rr++) {
                int r = rB + rr * 8;
                if (r < M) {
#pragma unroll
                    for (int c2 = 0; c2 < 2; c2++) {
                        int c = cB + c2;
                        float v = mst[(mi * 4 + ni) * 4 + rr * 2 + c2];
                        size_t idx = (size_t)r * 256 + c;
                        if (MODE == 0) {
                            Cb[idx] = v;
                        } else if (MODE == 1) {
                            Cb[idx] = 1.f / (1.f + expf(-v));
                        } else if (MODE == 2) {
                            float z = 1.f / (1.f + expf(-(v + bias[c])));
                            Cb[idx] = (1.f - z) * aux1[idx] + z * aux2[idx];
                        } else {
                            float t = tanhf(v);
                            float z = aux1[idx];
                            Cb[idx] = (1.f - z) * aux2[idx] + z * t;
                        }
                    }
                }
            }
        }
    }
}

// ---------------- fused weight transpose (all 4 weights, one launch) ----------------
__global__ void k_transW(const float* __restrict__ Wf, const float* __restrict__ Wz,
                         const float* __restrict__ Wr, const float* __restrict__ Wt,
                         float* __restrict__ WfT, float* __restrict__ WzT,
                         float* __restrict__ WrT, float* __restrict__ WtT)
{
    __shared__ float t[32][33];
    int x = threadIdx.x, y = threadIdx.y;
    const float* srcs[4] = {Wf, Wz, Wr, Wt};
    float* dsts[4] = {WfT, WzT, WrT, WtT};
    const int Cs[4] = {1024, 512, 512, 512};
#pragma unroll
    for (int w = 0; w < 4; w++) {
        int C = Cs[w];
        const int R = 256;
        if (blockIdx.x * 32 >= C) continue;   // uniform per block
        int bx = blockIdx.x * 32, by = blockIdx.y * 32;
        __syncthreads();
#pragma unroll
        for (int j = 0; j < 32; j += 8) {
            int r = by + y + j, c = bx + x;
            t[y + j][x] = srcs[w][(size_t)r * C + c];
        }
        __syncthreads();
#pragma unroll
        for (int j = 0; j < 32; j += 8) {
            int r = bx + y + j, c = by + x;
            dsts[w][(size_t)r * R + c] = t[x][y + j];
        }
    }
}

// ---------------- host side ----------------
template<int MODE, int FOLD>
static void run_frag(const float* pA, const float* pB, float* C, int M, int MT, int KT, int batch,
                     const float* bias, const float* a1, const float* a2)
{
    cudaFuncSetAttribute(gemm_frag<MODE, FOLD>, cudaFuncAttributeMaxDynamicSharedMemorySize, FRAG_SMEM);
    dim3 grid(2, MT, batch);
    gemm_frag<MODE, FOLD><<<grid, 256, FRAG_SMEM>>>(pA, pB, C, M, MT, KT, bias, a1, a2);
}

extern "C" void kernel_launch(void* const* d_in, const int* in_sizes, int n_in,
                              void* d_out, int out_size)
{
    const float* node_feature = (const float*)d_in[0];
    const float* node2edge    = (const float*)d_in[1];
    const float* edge2node    = (const float*)d_in[2];
    const float* Wz = (const float*)d_in[3];
    const float* Wr = (const float*)d_in[4];
    const float* Wt = (const float*)d_in[5];
    const float* Wf = (const float*)d_in[6];
    const float* bf = (const float*)d_in[7];
    float* out = (float*)d_out;

    float *pA1, *pA2, *pA3, *pA4, *pBnf, *pBt1, *pBt2, *pAct, *pWf, *pWz, *pWr, *pWt;
    float *tmp1, *tmp2, *bwP, *fwP, *agg, *zg, *rg, *nf1;
    float *WfT, *WzT, *WrT, *WtT;
    cudaGetSymbolAddress((void**)&pA1, g_pA1);
    cudaGetSymbolAddress((void**)&pA2, g_pA2);
    cudaGetSymbolAddress((void**)&pA3, g_pA3);
    cudaGetSymbolAddress((void**)&pA4, g_pA4);
    cudaGetSymbolAddress((void**)&pBnf, g_pBnf);
    cudaGetSymbolAddress((void**)&pBt1, g_pBt1);
    cudaGetSymbolAddress((void**)&pBt2, g_pBt2);
    cudaGetSymbolAddress((void**)&pAct, g_pAct);
    cudaGetSymbolAddress((void**)&pWf, g_pWf);
    cudaGetSymbolAddress((void**)&pWz, g_pWz);
    cudaGetSymbolAddress((void**)&pWr, g_pWr);
    cudaGetSymbolAddress((void**)&pWt, g_pWt);
    cudaGetSymbolAddress((void**)&tmp1, g_tmp1);
    cudaGetSymbolAddress((void**)&tmp2, g_tmp2);
    cudaGetSymbolAddress((void**)&bwP,  g_bw);
    cudaGetSymbolAddress((void**)&fwP,  g_fw);
    cudaGetSymbolAddress((void**)&agg,  g_agg);
    cudaGetSymbolAddress((void**)&zg,   g_zg);
    cudaGetSymbolAddress((void**)&rg,   g_rg);
    cudaGetSymbolAddress((void**)&nf1,  g_nf1);
    cudaGetSymbolAddress((void**)&WfT,  g_WfT);
    cudaGetSymbolAddress((void**)&WzT,  g_WzT);
    cudaGetSymbolAddress((void**)&WrT,  g_WrT);
    cudaGetSymbolAddress((void**)&WtT,  g_WtT);

    // weights: one fused transpose launch, then B-images
    k_transW<<<dim3(32, 8), dim3(32, 8)>>>(Wf, Wz, Wr, Wt, WfT, WzT, WrT, WtT);
    k_packB<<<dim3(KTF, 2, 1), 256>>>(WfT, pWf, 4 * HH, KTF);
    k_packB<<<dim3(KTG, 2, 1), 256>>>(WzT, pWz, 2 * HH, KTG);
    k_packB<<<dim3(KTG, 2, 1), 256>>>(WrT, pWr, 2 * HH, KTG);
    k_packB<<<dim3(KTG, 2, 1), 256>>>(WtT, pWt, 2 * HH, KTG);

    const long long sPQ = (long long)EE * NN;
    const int MR = BB * NN;   // 8000

    // pack adjacency fragment images (reused both hops)
    k_packA<0><<<dim3(KT12, MT12, BB), 256>>>(node2edge, pA1, EE, NN, NN, sPQ, MT12, KT12);
    k_packA<1><<<dim3(KT12, MT12, BB), 256>>>(edge2node, pA2, EE, NN, EE, sPQ, MT12, KT12);
    k_packA<0><<<dim3(KT34, MT34, BB), 256>>>(edge2node, pA3, NN, EE, EE, sPQ, MT34, KT34);
    k_packA<1><<<dim3(KT34, MT34, BB), 256>>>(node2edge, pA4, NN, EE, NN, sPQ, MT34, KT34);

    const float* nfIn = node_feature;
    for (int hop = 0; hop < 2; hop++) {
        float* nfOut = (hop == 1) ? out : nf1;

        // pack nf as B image
        k_packB<<<dim3(KT12, 2, BB), 256>>>(nfIn, pBnf, NN, KT12);

        // tmp1 = node2edge @ nf ; tmp2 = edge2node^T @ nf
        run_frag<0, 4>(pA1, pBnf, tmp1, EE, MT12, KT12, BB, nullptr, nullptr, nullptr);
        run_frag<0, 4>(pA2, pBnf, tmp2, EE, MT12, KT12, BB, nullptr, nullptr, nullptr);

        // pack tmp1/tmp2 as B images
        k_packB<<<dim3(KT34, 2, BB), 256>>>(tmp1, pBt1, EE, KT34);
        k_packB<<<dim3(KT34, 2, BB), 256>>>(tmp2, pBt2, EE, KT34);

        // bw = edge2node @ tmp1 ; fw = node2edge^T @ tmp2
        run_frag<0, 4>(pA3, pBt1, bwP, NN, MT34, KT34, BB, nullptr, nullptr, nullptr);
        run_frag<0, 4>(pA4, pBt2, fwP, NN, MT34, KT34, BB, nullptr, nullptr, nullptr);

        // gated fusion: agg = (1-z)*fw + z*bw, z = sigmoid(cat4 @ WfT + bf)
        // cat4 built on the fly inside the pack (bit-identical values)
        k_packA_f<0><<<dim3(KTF, MTS), 256>>>(fwP, bwP, nullptr, pAct, KTF);
        run_frag<2, 1>(pAct, pWf, agg, MR, MTS, KTF, 1, bf, fwP, bwP);

        // GRU step (hx / cat2 built on the fly inside the packs)
        k_packA_f<1><<<dim3(KTG, MTS), 256>>>(nfIn, agg, nullptr, pAct, KTG);
        run_frag<1, 1>(pAct, pWz, zg, MR, MTS, KTG, 1, nullptr, nullptr, nullptr);
        run_frag<1, 1>(pAct, pWr, rg, MR, MTS, KTG, 1, nullptr, nullptr, nullptr);
        k_packA_f<2><<<dim3(KTG, MTS), 256>>>(rg, nfIn, agg, pAct, KTG);
        run_frag<3, 1>(pAct, pWt, nfOut, MR, MTS, KTG, 1, nullptr, zg, nfIn);

        nfIn = nfOut;
    }
}

// round 12
// speedup vs baseline: 2.4215x; 1.0255x over previous
#include <cuda_runtime.h>
#include <cstdint>
#include <math.h>

// ---------------- problem constants ----------------
#define BB 8
#define NN 1000
#define EE 4000
#define HH 256

// GEMM tiling: CTA tile 128x64 (grid.x=4), k-tile 16. Fragment images unchanged:
// A image per (b, mtile, ktile): 4096 floats = [hi 2048][lo 2048] in mma-fragment order.
// B image per (b, ktile, nt2):   4096 floats, nt2 = 128-col half; CTA reads its 64-col half.
#define MT12 32      // GEMM1/2: M=4000 -> 32 tiles of 128
#define KT12 63      // K=1000  -> 63 tiles of 16
#define MT34 8       // GEMM3/4: M=1000 -> 8 tiles
#define KT34 250     // K=4000  -> 250 tiles

// small-GEMM tiling: M=8000 -> 63 tiles; K=1024 -> 64 kt; K=512 -> 32 kt
#define MTS 63
#define KTF 64
#define KTG 32

#define PA12_SZ (MT12*KT12*4096*BB)
#define PA34_SZ (MT34*KT34*4096*BB)
#define PB_NF_SZ (KT12*2*4096*BB)
#define PB_T_SZ  (KT34*2*4096*BB)
#define PACT_SZ  (MTS*KTF*4096)      // reused sequentially for cat4 / hx / cat2 images

// ---------------- scratch (static device globals; no allocation) ----------------
__device__ float g_pA1[PA12_SZ];
__device__ float g_pA2[PA12_SZ];
__device__ float g_pA3[PA34_SZ];
__device__ float g_pA4[PA34_SZ];
__device__ float g_pBnf[PB_NF_SZ];
__device__ float g_pBt1[PB_T_SZ];
__device__ float g_pBt2[PB_T_SZ];
__device__ float g_pAct[PACT_SZ];
__device__ float g_pWf[KTF*2*4096];
__device__ float g_pWz[KTG*2*4096];
__device__ float g_pWr[KTG*2*4096];
__device__ float g_pWt[KTG*2*4096];

__device__ float g_tmp1[BB*EE*HH];
__device__ float g_tmp2[BB*EE*HH];
__device__ float g_bw  [BB*NN*HH];
__device__ float g_fw  [BB*NN*HH];
__device__ float g_agg [BB*NN*HH];
__device__ float g_zg  [BB*NN*HH];
__device__ float g_rg  [BB*NN*HH];
__device__ float g_nf1 [BB*NN*HH];
__device__ float g_WfT [4*HH*HH];
__device__ float g_WzT [2*HH*HH];
__device__ float g_WrT [2*HH*HH];
__device__ float g_WtT [2*HH*HH];

// ---------------- helpers ----------------
__device__ __forceinline__ uint32_t f2tf(float f) {
    uint32_t u; asm("cvt.rna.tf32.f32 %0, %1;" : "=r"(u) : "f"(f)); return u;
}

__device__ __forceinline__ void split2(float x, float& h, float& l) {
    uint32_t hu = f2tf(x);
    h = __uint_as_float(hu);
    float r1 = __fadd_rn(x, -h);
    uint32_t lu = f2tf(r1);
    l = __uint_as_float(lu);
}

__device__ __forceinline__ void mma8(float* d, const uint32_t* a, uint32_t b0, uint32_t b1) {
    asm volatile(
        "mma.sync.aligned.m16n8k8.row.col.f32.tf32.tf32.f32 "
        "{%0,%1,%2,%3},{%4,%5,%6,%7},{%8,%9},{%0,%1,%2,%3};"
        : "+f"(d[0]), "+f"(d[1]), "+f"(d[2]), "+f"(d[3])
        : "r"(a[0]), "r"(a[1]), "r"(a[2]), "r"(a[3]), "r"(b0), "r"(b1));
}

__device__ __forceinline__ void cp_async16(float4* smem_ptr, const float4* gptr) {
    uint32_t s = (uint32_t)__cvta_generic_to_shared(smem_ptr);
    asm volatile("cp.async.cg.shared.global [%0], [%1], 16;" :: "r"(s), "l"(gptr));
}
__device__ __forceinline__ void cp_commit() {
    asm volatile("cp.async.commit_group;");
}
template<int N>
__device__ __forceinline__ void cp_wait() {
    asm volatile("cp.async.wait_group %0;" :: "n"(N));
}

// fragment offset for A element (mRel in [0,128), kRel in [0,16)) within 2048-float plane
__device__ __forceinline__ int a_frag_off(int mRel, int kRel) {
    int ms = mRel >> 4;
    int ks2 = kRel >> 3;
    int lane = (mRel & 7) * 4 + (kRel & 3);
    int areg = ((kRel >> 2) & 1) * 2 + ((mRel >> 3) & 1);
    return (((ms * 2) + ks2) * 32 + lane) * 4 + areg;
}
// fragment offset for B element (kRel in [0,16), nRel in [0,128))
__device__ __forceinline__ int b_frag_off(int kRel, int nRel) {
    int ns = nRel >> 3;
    int lane = (nRel & 7) * 4 + (kRel & 3);
    int breg = ((kRel >> 3) & 1) * 2 + ((kRel >> 2) & 1);
    return (ns * 32 + lane) * 4 + breg;
}

// ---------------- pack kernels ----------------
template<int TRANSA>
__global__ void __launch_bounds__(256)
k_packA(const float* __restrict__ src, float* __restrict__ dst,
        int M, int K, int lda, long long sSrc, int MT, int KT)
{
    __shared__ float img[4096];
    int kt = blockIdx.x, mt = blockIdx.y, b = blockIdx.z;
    const float* S = src + (long long)b * sSrc;
    int m0 = mt * 128, k0 = kt * 16;
    int tid = threadIdx.x;
#pragma unroll
    for (int it = 0; it < 2; it++) {
        int linear = tid + it * 256;
        float4 v = make_float4(0.f, 0.f, 0.f, 0.f);
        int mR[4], kR[4];
        if (TRANSA == 0) {
            int row = linear >> 2, c4 = (linear & 3) << 2;
            int gm = m0 + row, gk = k0 + c4;
            if (gm < M) {
                if (gk + 3 < K) v = *reinterpret_cast<const float4*>(S + (size_t)gm * lda + gk);
                else {
                    float* p = &v.x;
#pragma unroll
                    for (int j = 0; j < 4; j++) if (gk + j < K) p[j] = S[(size_t)gm * lda + gk + j];
                }
            }
#pragma unroll
            for (int j = 0; j < 4; j++) { mR[j] = row; kR[j] = c4 + j; }
        } else {
            int kk = linear >> 5, m4 = (linear & 31) << 2;
            int gk = k0 + kk, gm = m0 + m4;
            if (gk < K) {
                if (gm + 3 < M) v = *reinterpret_cast<const float4*>(S + (size_t)gk * lda + gm);
                else {
                    float* p = &v.x;
#pragma unroll
                    for (int j = 0; j < 4; j++) if (gm + j < M) p[j] = S[(size_t)gk * lda + gm + j];
                }
            }
#pragma unroll
            for (int j = 0; j < 4; j++) { mR[j] = m4 + j; kR[j] = kk; }
        }
        const float* pv = &v.x;
#pragma unroll
        for (int j = 0; j < 4; j++) {
            float h, l;
            split2(pv[j], h, l);
            int off = a_frag_off(mR[j], kR[j]);
            img[off] = h; img[2048 + off] = l;
        }
    }
    __syncthreads();
    float4* D = reinterpret_cast<float4*>(dst + (((long long)b * MT + mt) * KT + kt) * 4096);
    const float4* I = reinterpret_cast<const float4*>(img);
#pragma unroll
    for (int i = 0; i < 4; i++) D[tid + i * 256] = I[tid + i * 256];
}

// Fused activation A-pack: builds cat4/hx/cat2 values on the fly (bit-identical values).
// SRC 0: cat4 [fw,bw,fw*bw,fw-bw] K=1024 (s1=fw, s2=bw)
// SRC 1: hx   [nf,agg]            K=512  (s1=nf, s2=agg)
// SRC 2: cat2 [rg*nf,agg]         K=512  (s1=rg, s2=nf, s3=agg)
template<int SRC>
__global__ void __launch_bounds__(256)
k_packA_f(const float* __restrict__ s1, const float* __restrict__ s2, const float* __restrict__ s3,
          float* __restrict__ dst, int KT)
{
    __shared__ float img[4096];
    int kt = blockIdx.x, mt = blockIdx.y;
    int m0 = mt * 128, k0 = kt * 16;
    int tid = threadIdx.x;
#pragma unroll
    for (int it = 0; it < 2; it++) {
        int linear = tid + it * 256;
        int row = linear >> 2, c4 = (linear & 3) << 2;
        int gm = m0 + row;
#pragma unroll
        for (int j = 0; j < 4; j++) {
            int gk = k0 + c4 + j;
            float val = 0.f;
            if (gm < BB * NN) {
                if (SRC == 0) {
                    int feat = gk >> 8, hcol = gk & 255;
                    float f = s1[(size_t)gm * 256 + hcol];
                    float b = s2[(size_t)gm * 256 + hcol];
                    val = (feat == 0) ? f : (feat == 1) ? b : (feat == 2) ? f * b : f - b;
                } else if (SRC == 1) {
                    val = (gk < 256) ? s1[(size_t)gm * 256 + gk]
                                     : s2[(size_t)gm * 256 + (gk - 256)];
                } else {
                    val = (gk < 256) ? s1[(size_t)gm * 256 + gk] * s2[(size_t)gm * 256 + gk]
                                     : s3[(size_t)gm * 256 + (gk - 256)];
                }
            }
            float h, l;
            split2(val, h, l);
            int off = a_frag_off(row, c4 + j);
            img[off] = h; img[2048 + off] = l;
        }
    }
    __syncthreads();
    float4* D = reinterpret_cast<float4*>(dst + ((long long)mt * KT + kt) * 4096);
    const float4* I = reinterpret_cast<const float4*>(img);
#pragma unroll
    for (int i = 0; i < 4; i++) D[tid + i * 256] = I[tid + i * 256];
}

__global__ void __launch_bounds__(256)
k_packB(const float* __restrict__ src, float* __restrict__ dst, int K, int KT)
{
    __shared__ float img[4096];
    int kt = blockIdx.x, nt = blockIdx.y, b = blockIdx.z;
    const float* S = src + (long long)b * K * 256;
    int k0 = kt * 16, n0 = nt * 128;
    int tid = threadIdx.x;
#pragma unroll
    for (int it = 0; it < 2; it++) {
        int linear = tid + it * 256;
        int kr = linear >> 5, n4 = (linear & 31) << 2;
        int gk = k0 + kr;
        float4 v = make_float4(0.f, 0.f, 0.f, 0.f);
        if (gk < K) v = *reinterpret_cast<const float4*>(S + (size_t)gk * 256 + n0 + n4);
        const float* pv = &v.x;
#pragma unroll
        for (int j = 0; j < 4; j++) {
            float h, l;
            split2(pv[j], h, l);
            int off = b_frag_off(kr, n4 + j);
            img[off] = h; img[2048 + off] = l;
        }
    }
    __syncthreads();
    float4* D = reinterpret_cast<float4*>(dst + (((long long)b * KT + kt) * 2 + nt) * 4096);
    const float4* I = reinterpret_cast<const float4*>(img);
#pragma unroll
    for (int i = 0; i < 4; i++) D[tid + i * 256] = I[tid + i * 256];
}

// ---------------- fragment GEMM: 128x64 CTA tile, 2 CTAs/SM, 4-stage ring ----------------
// MODE: 0=store, 1=sigmoid, 2=gated fusion (bias, aux1=fw, aux2=bw), 3=GRU out (aux1=z, aux2=h_old)
// FOLD: fold fresh accumulator into master every FOLD k-tiles (FOLD=1 precision-critical for
// fusion/GRU GEMMs — R6 regression)
#define STAGES_T 4
#define STAGE_FLOATS 6144            // A 4096 + B-half 2048
#define FRAG_SMEM (STAGES_T*STAGE_FLOATS*4)   // 98304 bytes

template<int MODE, int FOLD>
__global__ void __launch_bounds__(256, 2)
gemm_frag(const float* __restrict__ pA, const float* __restrict__ pB, float* __restrict__ C,
          int M, int MT, int KT,
          const float* __restrict__ bias,
          const float* __restrict__ aux1, const float* __restrict__ aux2)
{
    extern __shared__ float sm[];   // STAGES_T x (A 4096 + Bhalf 2048) floats
    const int tid = threadIdx.x;
    const int nt4 = blockIdx.x, mt = blockIdx.y, b = blockIdx.z;
    const int nt2 = nt4 >> 1, half = nt4 & 1;
    const float4* Abase = reinterpret_cast<const float4*>(pA) + ((long long)b * MT + mt) * KT * 1024;
    // B half source: image tile (kt,nt2), hi half at half*256 float4, lo half at 512+half*256
    const float4* Bbase = reinterpret_cast<const float4*>(pB) + (long long)b * KT * 2048;

    const int lane = tid & 31, warp = tid >> 5;
    const int wm = warp >> 2, wn = warp & 3;     // 2(m) x 4(n) warps -> 64x16 warp tiles
    const int gid = lane >> 2, tig = lane & 3;

    float acc[32], mst[32];
#pragma unroll
    for (int i = 0; i < 32; i++) { acc[i] = 0.f; mst[i] = 0.f; }

    auto issue = [&](int kt) {
        float4* s = reinterpret_cast<float4*>(sm + (kt % STAGES_T) * STAGE_FLOATS);
        const float4* A = Abase + (size_t)kt * 1024;
        const float4* Bt = Bbase + ((size_t)kt * 2 + nt2) * 1024;
#pragma unroll
        for (int i = 0; i < 4; i++) cp_async16(s + tid + i * 256, A + tid + i * 256);
        // B: hi half (256 float4) then lo half (256 float4)
        cp_async16(s + 1024 + tid, Bt + half * 256 + tid);
        cp_async16(s + 1280 + tid, Bt + 512 + half * 256 + tid);
    };
    auto issueG = [&](int g) {    // granule = 2 k-tiles, one commit group
        int kt0 = g * 2;
        if (kt0 < KT) issue(kt0);
        if (kt0 + 1 < KT) issue(kt0 + 1);
    };

    auto compute = [&](int stage) {
        const float* sA = sm + stage * STAGE_FLOATS;
        const float* sB = sm + stage * STAGE_FLOATS + 4096;   // [hi 1024][lo 1024]
        float4 bh[2], bl[2];
#pragma unroll
        for (int ni = 0; ni < 2; ni++) {
            int nsl = wn * 2 + ni;   // local n-slice 0..7
            bh[ni] = *reinterpret_cast<const float4*>(sB + (nsl * 32 + lane) * 4);
            bl[ni] = *reinterpret_cast<const float4*>(sB + 1024 + (nsl * 32 + lane) * 4);
        }
#pragma unroll
        for (int ks = 0; ks < 2; ks++) {
#pragma unroll
            for (int mi = 0; mi < 4; mi++) {
                int ms = wm * 4 + mi;
                float4 a4h = *reinterpret_cast<const float4*>(sA + ((ms * 2 + ks) * 32 + lane) * 4);
                float4 a4l = *reinterpret_cast<const float4*>(sA + 2048 + ((ms * 2 + ks) * 32 + lane) * 4);
                uint32_t ah[4] = {__float_as_uint(a4h.x), __float_as_uint(a4h.y),
                                  __float_as_uint(a4h.z), __float_as_uint(a4h.w)};
                uint32_t al[4] = {__float_as_uint(a4l.x), __float_as_uint(a4l.y),
                                  __float_as_uint(a4l.z), __float_as_uint(a4l.w)};
#pragma unroll
                for (int ni = 0; ni < 2; ni++) {
                    float* a4 = &acc[(mi * 2 + ni) * 4];
                    uint32_t bhk0 = (ks == 0) ? __float_as_uint(bh[ni].x) : __float_as_uint(bh[ni].z);
                    uint32_t bhk1 = (ks == 0) ? __float_as_uint(bh[ni].y) : __float_as_uint(bh[ni].w);
                    uint32_t blk0 = (ks == 0) ? __float_as_uint(bl[ni].x) : __float_as_uint(bl[ni].z);
                    uint32_t blk1 = (ks == 0) ? __float_as_uint(bl[ni].y) : __float_as_uint(bl[ni].w);
                    mma8(a4, al, bhk0, bhk1);
                    mma8(a4, ah, blk0, blk1);
                    mma8(a4, ah, bhk0, bhk1);
                }
            }
        }
    };

    auto fold = [&]() {
#pragma unroll
        for (int i = 0; i < 32; i++) { mst[i] = __fadd_rn(mst[i], acc[i]); acc[i] = 0.f; }
    };

    const int NG = (KT + 1) >> 1;
    issueG(0); cp_commit();
    issueG(1); cp_commit();

    for (int g = 0; g < NG; g++) {
        cp_wait<1>();
        __syncthreads();
        int kt = g * 2;
        compute(kt % STAGES_T);
        if (((kt + 1) % FOLD) == 0 || kt == KT - 1) fold();
        if (kt + 1 < KT) {
            compute((kt + 1) % STAGES_T);
            if (((kt + 2) % FOLD) == 0 || kt + 1 == KT - 1) fold();
        }
        __syncthreads();     // all warps done reading stage (g) before overwriting (4-stage ring)
        issueG(g + 2);
        cp_commit();
    }

    float* Cb = C + (long long)b * M * 256;
#pragma unroll
    for (int mi = 0; mi < 4; mi++) {
#pragma unroll
        for (int ni = 0; ni < 2; ni++) {
            int rB = mt * 128 + wm * 64 + mi * 16 + gid;
            int cB = nt4 * 64 + wn * 16 + ni * 8 + tig * 2;
#pragma unroll
            for (int rr = 0; rr < 2; rr++) {
                int r = rB + rr * 8;
                if (r < M) {
#pragma unroll
                    for (int c2 = 0; c2 < 2; c2++) {
                        int c = cB + c2;
                        float v = mst[(mi * 2 + ni) * 4 + rr * 2 + c2];
                        size_t idx = (size_t)r * 256 + c;
                        if (MODE == 0) {
                            Cb[idx] = v;
                        } else if (MODE == 1) {
                            Cb[idx] = 1.f / (1.f + expf(-v));
                        } else if (MODE == 2) {
                            float z = 1.f / (1.f + expf(-(v + bias[c])));
                            Cb[idx] = (1.f - z) * aux1[idx] + z * aux2[idx];
                        } else {
                            float t = tanhf(v);
                            float z = aux1[idx];
                            Cb[idx] = (1.f - z) * aux2[idx] + z * t;
                        }
                    }
                }
            }
        }
    }
}

// ---------------- fused weight transpose (all 4 weights, one launch) ----------------
__global__ void k_transW(const float* __restrict__ Wf, const float* __restrict__ Wz,
                         const float* __restrict__ Wr, const float* __restrict__ Wt,
                         float* __restrict__ WfT, float* __restrict__ WzT,
                         float* __restrict__ WrT, float* __restrict__ WtT)
{
    __shared__ float t[32][33];
    int x = threadIdx.x, y = threadIdx.y;
    const float* srcs[4] = {Wf, Wz, Wr, Wt};
    float* dsts[4] = {WfT, WzT, WrT, WtT};
    const int Cs[4] = {1024, 512, 512, 512};
#pragma unroll
    for (int w = 0; w < 4; w++) {
        int C = Cs[w];
        const int R = 256;
        if (blockIdx.x * 32 >= C) continue;
        int bx = blockIdx.x * 32, by = blockIdx.y * 32;
        __syncthreads();
#pragma unroll
        for (int j = 0; j < 32; j += 8) {
            int r = by + y + j, c = bx + x;
            t[y + j][x] = srcs[w][(size_t)r * C + c];
        }
        __syncthreads();
#pragma unroll
        for (int j = 0; j < 32; j += 8) {
            int r = bx + y + j, c = by + x;
            dsts[w][(size_t)r * R + c] = t[x][y + j];
        }
    }
}

// ---------------- host side ----------------
template<int MODE, int FOLD>
static void run_frag(const float* pA, const float* pB, float* C, int M, int MT, int KT, int batch,
                     const float* bias, const float* a1, const float* a2)
{
    cudaFuncSetAttribute(gemm_frag<MODE, FOLD>, cudaFuncAttributeMaxDynamicSharedMemorySize, FRAG_SMEM);
    dim3 grid(4, MT, batch);
    gemm_frag<MODE, FOLD><<<grid, 256, FRAG_SMEM>>>(pA, pB, C, M, MT, KT, bias, a1, a2);
}

extern "C" void kernel_launch(void* const* d_in, const int* in_sizes, int n_in,
                              void* d_out, int out_size)
{
    const float* node_feature = (const float*)d_in[0];
    const float* node2edge    = (const float*)d_in[1];
    const float* edge2node    = (const float*)d_in[2];
    const float* Wz = (const float*)d_in[3];
    const float* Wr = (const float*)d_in[4];
    const float* Wt = (const float*)d_in[5];
    const float* Wf = (const float*)d_in[6];
    const float* bf = (const float*)d_in[7];
    float* out = (float*)d_out;

    float *pA1, *pA2, *pA3, *pA4, *pBnf, *pBt1, *pBt2, *pAct, *pWf, *pWz, *pWr, *pWt;
    float *tmp1, *tmp2, *bwP, *fwP, *agg, *zg, *rg, *nf1;
    float *WfT, *WzT, *WrT, *WtT;
    cudaGetSymbolAddress((void**)&pA1, g_pA1);
    cudaGetSymbolAddress((void**)&pA2, g_pA2);
    cudaGetSymbolAddress((void**)&pA3, g_pA3);
    cudaGetSymbolAddress((void**)&pA4, g_pA4);
    cudaGetSymbolAddress((void**)&pBnf, g_pBnf);
    cudaGetSymbolAddress((void**)&pBt1, g_pBt1);
    cudaGetSymbolAddress((void**)&pBt2, g_pBt2);
    cudaGetSymbolAddress((void**)&pAct, g_pAct);
    cudaGetSymbolAddress((void**)&pWf, g_pWf);
    cudaGetSymbolAddress((void**)&pWz, g_pWz);
    cudaGetSymbolAddress((void**)&pWr, g_pWr);
    cudaGetSymbolAddress((void**)&pWt, g_pWt);
    cudaGetSymbolAddress((void**)&tmp1, g_tmp1);
    cudaGetSymbolAddress((void**)&tmp2, g_tmp2);
    cudaGetSymbolAddress((void**)&bwP,  g_bw);
    cudaGetSymbolAddress((void**)&fwP,  g_fw);
    cudaGetSymbolAddress((void**)&agg,  g_agg);
    cudaGetSymbolAddress((void**)&zg,   g_zg);
    cudaGetSymbolAddress((void**)&rg,   g_rg);
    cudaGetSymbolAddress((void**)&nf1,  g_nf1);
    cudaGetSymbolAddress((void**)&WfT,  g_WfT);
    cudaGetSymbolAddress((void**)&WzT,  g_WzT);
    cudaGetSymbolAddress((void**)&WrT,  g_WrT);
    cudaGetSymbolAddress((void**)&WtT,  g_WtT);

    // weights: one fused transpose launch, then B-images
    k_transW<<<dim3(32, 8), dim3(32, 8)>>>(Wf, Wz, Wr, Wt, WfT, WzT, WrT, WtT);
    k_packB<<<dim3(KTF, 2, 1), 256>>>(WfT, pWf, 4 * HH, KTF);
    k_packB<<<dim3(KTG, 2, 1), 256>>>(WzT, pWz, 2 * HH, KTG);
    k_packB<<<dim3(KTG, 2, 1), 256>>>(WrT, pWr, 2 * HH, KTG);
    k_packB<<<dim3(KTG, 2, 1), 256>>>(WtT, pWt, 2 * HH, KTG);

    const long long sPQ = (long long)EE * NN;
    const int MR = BB * NN;   // 8000

    // pack adjacency fragment images (reused both hops)
    k_packA<0><<<dim3(KT12, MT12, BB), 256>>>(node2edge, pA1, EE, NN, NN, sPQ, MT12, KT12);
    k_packA<1><<<dim3(KT12, MT12, BB), 256>>>(edge2node, pA2, EE, NN, EE, sPQ, MT12, KT12);
    k_packA<0><<<dim3(KT34, MT34, BB), 256>>>(edge2node, pA3, NN, EE, EE, sPQ, MT34, KT34);
    k_packA<1><<<dim3(KT34, MT34, BB), 256>>>(node2edge, pA4, NN, EE, NN, sPQ, MT34, KT34);

    const float* nfIn = node_feature;
    for (int hop = 0; hop < 2; hop++) {
        float* nfOut = (hop == 1) ? out : nf1;

        // pack nf as B image
        k_packB<<<dim3(KT12, 2, BB), 256>>>(nfIn, pBnf, NN, KT12);

        // tmp1 = node2edge @ nf ; tmp2 = edge2node^T @ nf
        run_frag<0, 4>(pA1, pBnf, tmp1, EE, MT12, KT12, BB, nullptr, nullptr, nullptr);
        run_frag<0, 4>(pA2, pBnf, tmp2, EE, MT12, KT12, BB, nullptr, nullptr, nullptr);

        // pack tmp1/tmp2 as B images
        k_packB<<<dim3(KT34, 2, BB), 256>>>(tmp1, pBt1, EE, KT34);
        k_packB<<<dim3(KT34, 2, BB), 256>>>(tmp2, pBt2, EE, KT34);

        // bw = edge2node @ tmp1 ; fw = node2edge^T @ tmp2
        run_frag<0, 4>(pA3, pBt1, bwP, NN, MT34, KT34, BB, nullptr, nullptr, nullptr);
        run_frag<0, 4>(pA4, pBt2, fwP, NN, MT34, KT34, BB, nullptr, nullptr, nullptr);

        // gated fusion: agg = (1-z)*fw + z*bw, z = sigmoid(cat4 @ WfT + bf)
        k_packA_f<0><<<dim3(KTF, MTS), 256>>>(fwP, bwP, nullptr, pAct, KTF);
        run_frag<2, 1>(pAct, pWf, agg, MR, MTS, KTF, 1, bf, fwP, bwP);

        // GRU step (hx / cat2 built on the fly inside the packs)
        k_packA_f<1><<<dim3(KTG, MTS), 256>>>(nfIn, agg, nullptr, pAct, KTG);
        run_frag<1, 1>(pAct, pWz, zg, MR, MTS, KTG, 1, nullptr, nullptr, nullptr);
        run_frag<1, 1>(pAct, pWr, rg, MR, MTS, KTG, 1, nullptr, nullptr, nullptr);
        k_packA_f<2><<<dim3(KTG, MTS), 256>>>(rg, nfIn, agg, pAct, KTG);
        run_frag<3, 1>(pAct, pWt, nfOut, MR, MTS, KTG, 1, nullptr, zg, nfIn);

        nfIn = nfOut;
    }
}